// round 3
// baseline (speedup 1.0000x reference)
#include <cuda_runtime.h>
#include <math.h>

// Problem constants (fixed by the reference)
#define NN      1000      // codeword length
#define KK      500       // info bits
#define MM      500       // parity checks
#define NUE     4
#define NBS     4
#define BPS     4
#define NSYM    250       // NN / BPS
#define NITER   5
#define BATCH   1000
#define NCW     4000      // BATCH * NUE  (codewords)
#define NROW    250000    // BATCH * NSYM (LMMSE rows)
#define NEDGE   2000
#define RSQRT2  0.70710678118654752f

// ---------------- scratch (device globals; no allocation allowed) -----------
__device__ unsigned char g_cbits[NCW * NN];          // 4 MB  codeword bits
__device__ float2        g_xf[NROW * NUE];           // 8 MB  tx symbols (row-major, ue fastest)
__device__ float         g_Lch[NN * NCW];            // 16 MB channel LLRs [n][cw]
__device__ float         g_c2v[NEDGE * NCW];         // 32 MB check->var messages [e][cw]
__device__ float         g_vtot[NN * NCW];           // 16 MB var totals [n][cw]
__device__ int           g_coff[MM + 1];             // check CSR offsets
__device__ int           g_cedge[NEDGE];             // edge ids sorted by check (stable)
__device__ int           g_voff[NN + 1];             // var CSR offsets
__device__ int           g_vedge[NEDGE];             // edge ids sorted by var (stable)

// 16-QAM constellation (matches reference POINTS)
__constant__ float2 c_pts[16] = {
    { 0.31622776601683794f,  0.31622776601683794f}, { 0.31622776601683794f,  0.9486832980505138f},
    { 0.9486832980505138f,   0.31622776601683794f}, { 0.9486832980505138f,   0.9486832980505138f},
    { 0.31622776601683794f, -0.31622776601683794f}, { 0.31622776601683794f, -0.9486832980505138f},
    { 0.9486832980505138f,  -0.31622776601683794f}, { 0.9486832980505138f,  -0.9486832980505138f},
    {-0.31622776601683794f,  0.31622776601683794f}, {-0.31622776601683794f,  0.9486832980505138f},
    {-0.9486832980505138f,   0.31622776601683794f}, {-0.9486832980505138f,   0.9486832980505138f},
    {-0.31622776601683794f, -0.31622776601683794f}, {-0.31622776601683794f, -0.9486832980505138f},
    {-0.9486832980505138f,  -0.31622776601683794f}, {-0.9486832980505138f,  -0.9486832980505138f}
};

// ---------------- complex helpers -------------------------------------------
struct C2 { float x, y; };
__device__ __forceinline__ C2 cmul(C2 a, C2 b)  { return { a.x*b.x - a.y*b.y, a.x*b.y + a.y*b.x }; }
__device__ __forceinline__ C2 cmulc(C2 a, C2 b) { return { a.x*b.x + a.y*b.y, a.y*b.x - a.x*b.y }; } // a*conj(b)
__device__ __forceinline__ C2 cadd(C2 a, C2 b)  { return { a.x + b.x, a.y + b.y }; }
__device__ __forceinline__ C2 csub(C2 a, C2 b)  { return { a.x - b.x, a.y - b.y }; }
__device__ __forceinline__ C2 cinv(C2 a) { float s = 1.0f/(a.x*a.x + a.y*a.y); return { a.x*s, -a.y*s }; }

// ---------------- setup: build deterministic CSR adjacency ------------------
__global__ void setup_csr_kernel(const int* __restrict__ cn, const int* __restrict__ vn) {
    __shared__ int scn[NEDGE];
    __shared__ int svn[NEDGE];
    __shared__ int ccnt[MM];
    __shared__ int vcnt[NN];
    __shared__ int coff[MM + 1];
    __shared__ int voff[NN + 1];
    int t = threadIdx.x;
    for (int e = t; e < NEDGE; e += blockDim.x) { scn[e] = cn[e]; svn[e] = vn[e]; }
    for (int i = t; i < MM; i += blockDim.x) ccnt[i] = 0;
    for (int i = t; i < NN; i += blockDim.x) vcnt[i] = 0;
    __syncthreads();
    for (int e = t; e < NEDGE; e += blockDim.x) {
        atomicAdd(&ccnt[scn[e]], 1);
        atomicAdd(&vcnt[svn[e]], 1);
    }
    __syncthreads();
    if (t == 0) { int a = 0; for (int i = 0; i < MM; i++) { coff[i] = a; a += ccnt[i]; } coff[MM] = a; }
    if (t == 1) { int a = 0; for (int i = 0; i < NN; i++) { voff[i] = a; a += vcnt[i]; } voff[NN] = a; }
    __syncthreads();
    // deterministic stable placement: rank = #earlier edges with same check/var
    for (int e = t; e < NEDGE; e += blockDim.x) {
        int c = scn[e], rc = 0;
        int v = svn[e], rv = 0;
        for (int q = 0; q < e; q++) {
            rc += (scn[q] == c);
            rv += (svn[q] == v);
        }
        g_cedge[coff[c] + rc] = e;
        g_vedge[voff[v] + rv] = e;
    }
    for (int i = t; i <= MM; i += blockDim.x) g_coff[i] = coff[i];
    for (int i = t; i <= NN; i += blockDim.x) g_voff[i] = voff[i];
}

// ---------------- encode ----------------------------------------------------
// out bf half + stash info bits
__global__ void bits_kernel(const int* __restrict__ b, float* __restrict__ out) {
    int tid = blockIdx.x * blockDim.x + threadIdx.x;   // over BATCH*NUE*KK = 2e6
    if (tid >= NCW * KK) return;
    int cw = tid / KK, i = tid % KK;
    int v = b[tid];
    out[tid] = (float)v;
    g_cbits[cw * NN + i] = (unsigned char)v;
}

// parity[j] = XOR of info bits on check j's edges
__global__ void parity_kernel(const int* __restrict__ vn) {
    int tid = blockIdx.x * blockDim.x + threadIdx.x;   // over NCW*MM = 2e6, j fastest
    if (tid >= NCW * MM) return;
    int cw = tid / MM, j = tid % MM;
    int b0 = g_coff[j], b1 = g_coff[j + 1];
    unsigned int acc = 0;
    for (int k = b0; k < b1; k++) {
        int e = g_cedge[k];
        int v = vn[e];
        if (v < KK) acc ^= g_cbits[cw * NN + v];
    }
    g_cbits[cw * NN + KK + j] = (unsigned char)(acc & 1u);
}

// map 4 bits -> 16QAM symbol; layout g_xf[(b*NSYM+s)*NUE + u]
__global__ void map_kernel() {
    int tid = blockIdx.x * blockDim.x + threadIdx.x;   // over NCW*NSYM = 1e6
    if (tid >= NCW * NSYM) return;
    int cw = tid / NSYM, s = tid % NSYM;
    int b = cw / NUE, u = cw % NUE;
    const unsigned char* cb = &g_cbits[cw * NN + s * 4];
    int idx = (cb[0] << 3) | (cb[1] << 2) | (cb[2] << 1) | cb[3];
    g_xf[(b * NSYM + s) * NUE + u] = c_pts[idx];
}

// ---------------- LMMSE detect + max-log demap ------------------------------
__global__ void lmmse_kernel(const float* __restrict__ h_re, const float* __restrict__ h_im,
                             const float* __restrict__ n_re, const float* __restrict__ n_im,
                             const float* __restrict__ ebno) {
    int r = blockIdx.x * blockDim.x + threadIdx.x;
    if (r >= NROW) return;

    float no  = 1.0f / (exp10f(ebno[0] * 0.1f) * (float)BPS * 0.5f);
    float wsc = sqrtf(no * 0.5f);

    C2 h[NBS][NUE];
    const float* hr = h_re + (size_t)r * 16;
    const float* hi = h_im + (size_t)r * 16;
#pragma unroll
    for (int i = 0; i < NBS; i++)
#pragma unroll
        for (int j = 0; j < NUE; j++)
            h[i][j] = { hr[i*4 + j] * RSQRT2, hi[i*4 + j] * RSQRT2 };

    // y = h x + w
    C2 y[NBS];
#pragma unroll
    for (int i = 0; i < NBS; i++) {
        C2 acc = { n_re[r*4 + i] * wsc, n_im[r*4 + i] * wsc };
#pragma unroll
        for (int j = 0; j < NUE; j++) {
            float2 xj = g_xf[r*4 + j];
            acc = cadd(acc, cmul(h[i][j], {xj.x, xj.y}));
        }
        y[i] = acc;
    }

    // augmented [A | y | h], A = h h^H + no I
    C2 Mx[4][9];
#pragma unroll
    for (int i = 0; i < 4; i++) {
#pragma unroll
        for (int k = 0; k < 4; k++) {
            C2 a = { (i == k) ? no : 0.0f, 0.0f };
#pragma unroll
            for (int j = 0; j < 4; j++) a = cadd(a, cmulc(h[i][j], h[k][j]));
            Mx[i][k] = a;
        }
        Mx[i][4] = y[i];
#pragma unroll
        for (int j = 0; j < 4; j++) Mx[i][5 + j] = h[i][j];
    }

    // LU elimination with partial pivoting (LAPACK cabs1 = |re|+|im|)
#pragma unroll
    for (int k = 0; k < 4; k++) {
        int p = k;
        float best = fabsf(Mx[k][k].x) + fabsf(Mx[k][k].y);
#pragma unroll
        for (int q = k + 1; q < 4; q++) {
            float m = fabsf(Mx[q][k].x) + fabsf(Mx[q][k].y);
            if (m > best) { best = m; p = q; }
        }
        if (p != k) {
#pragma unroll
            for (int c = 0; c < 9; c++) { C2 tmp = Mx[k][c]; Mx[k][c] = Mx[p][c]; Mx[p][c] = tmp; }
        }
        C2 piv_inv = cinv(Mx[k][k]);
#pragma unroll
        for (int rr = k + 1; rr < 4; rr++) {
            C2 f = cmul(Mx[rr][k], piv_inv);
#pragma unroll
            for (int c = k + 1; c < 9; c++) Mx[rr][c] = csub(Mx[rr][c], cmul(f, Mx[k][c]));
        }
    }
    // back substitution for all 5 RHS (in place)
    C2 dinv[4];
#pragma unroll
    for (int i = 0; i < 4; i++) dinv[i] = cinv(Mx[i][i]);
#pragma unroll
    for (int c = 4; c < 9; c++) {
#pragma unroll
        for (int rr = 3; rr >= 0; rr--) {
            C2 val = Mx[rr][c];
#pragma unroll
            for (int q = 0; q < 4; q++)
                if (q > rr) val = csub(val, cmul(Mx[rr][q], Mx[q][c]));
            Mx[rr][c] = cmul(val, dinv[rr]);
        }
    }

    int b = r / NSYM, s = r % NSYM;
    // per-UE: x_raw, diag, demap
#pragma unroll
    for (int j = 0; j < NUE; j++) {
        C2 xraw = {0.f, 0.f};
        float d = 0.f;
#pragma unroll
        for (int i = 0; i < 4; i++) {
            xraw = cadd(xraw, cmulc(Mx[i][4], h[i][j]));      // conj(h[i][j]) * z_y[i]
            C2 gw = cmulc(Mx[i][5 + j], h[i][j]);             // conj(h[i][j]) * (A^-1 h)[i][j]
            d += gw.x;
        }
        float inv_d = 1.0f / d;
        float xr = xraw.x * inv_d, xi = xraw.y * inv_d;
        float noe = fmaxf(inv_d - 1.0f, 1e-12f);
        float inv_nv = 1.0f / noe;

        float best0[4] = {3.4e38f, 3.4e38f, 3.4e38f, 3.4e38f};
        float best1[4] = {3.4e38f, 3.4e38f, 3.4e38f, 3.4e38f};
#pragma unroll
        for (int p = 0; p < 16; p++) {
            float dr = xr - c_pts[p].x, di = xi - c_pts[p].y;
            float d2 = dr * dr + di * di;
#pragma unroll
            for (int k = 0; k < 4; k++) {
                if ((p >> (3 - k)) & 1) best1[k] = fminf(best1[k], d2);
                else                    best0[k] = fminf(best0[k], d2);
            }
        }
        int cw = b * NUE + j;
#pragma unroll
        for (int k = 0; k < 4; k++) {
            float llr = (best1[k] - best0[k]) * inv_nv;   // m0 - m1
            g_Lch[(size_t)(s * 4 + k) * NCW + cw] = llr;
        }
    }
}

// ---------------- LDPC sum-product ------------------------------------------
__global__ void zero_c2v_kernel() {
    int tid = blockIdx.x * blockDim.x + threadIdx.x;
    if (tid < NEDGE * NCW) g_c2v[tid] = 0.0f;
}

__global__ void var_update_kernel() {
    int tid = blockIdx.x * blockDim.x + threadIdx.x;   // v*NCW + cw
    if (tid >= NN * NCW) return;
    int v = tid / NCW, cw = tid % NCW;
    float s = g_Lch[tid];
    int b0 = g_voff[v], b1 = g_voff[v + 1];
    for (int k = b0; k < b1; k++) {
        int e = g_vedge[k];
        s += g_c2v[(size_t)e * NCW + cw];
    }
    g_vtot[tid] = s;
}

__device__ __forceinline__ float tanh_clamped(float m) {
    float a = fminf(fmaxf(0.5f * m, -9.9f), 9.9f);
    float t = tanhf(a);
    return (t >= 0.0f) ? fmaxf(t, 1e-7f) : fminf(t, -1e-7f);
}

__global__ void check_update_kernel(const int* __restrict__ vn) {
    int tid = blockIdx.x * blockDim.x + threadIdx.x;   // j*NCW + cw
    if (tid >= MM * NCW) return;
    int j = tid / NCW, cw = tid % NCW;
    int b0 = g_coff[j], b1 = g_coff[j + 1];
    float prod = 1.0f;
    for (int k = b0; k < b1; k++) {
        int e = g_cedge[k];
        int v = vn[e];
        float m = g_vtot[(size_t)v * NCW + cw] - g_c2v[(size_t)e * NCW + cw];
        prod *= tanh_clamped(m);
    }
    for (int k = b0; k < b1; k++) {
        int e = g_cedge[k];
        int v = vn[e];
        float m = g_vtot[(size_t)v * NCW + cw] - g_c2v[(size_t)e * NCW + cw];
        float t = tanh_clamped(m);
        float ratio = prod / t;
        ratio = fminf(fmaxf(ratio, -0.999999f), 0.999999f);
        g_c2v[(size_t)e * NCW + cw] = 2.0f * atanhf(ratio);
    }
}

__global__ void bhat_kernel(float* __restrict__ out) {
    int tid = blockIdx.x * blockDim.x + threadIdx.x;   // cw*KK + i
    if (tid >= NCW * KK) return;
    int cw = tid / KK, i = tid % KK;
    out[(size_t)NCW * KK + tid] = (g_vtot[(size_t)i * NCW + cw] < 0.0f) ? 1.0f : 0.0f;
}

// ---------------- launch ----------------------------------------------------
extern "C" void kernel_launch(void* const* d_in, const int* in_sizes, int n_in,
                              void* d_out, int out_size) {
    // inputs: [batch_size?] ebno_db b P cn_idx vn_idx h_re h_im noise_re noise_im
    int base = n_in - 9;
    const float* ebno = (const float*)d_in[base + 0];
    const int*   b    = (const int*)  d_in[base + 1];
    // d_in[base+2] = P (unused; adjacency comes from edge lists)
    const int*   cn   = (const int*)  d_in[base + 3];
    const int*   vn   = (const int*)  d_in[base + 4];
    const float* h_re = (const float*)d_in[base + 5];
    const float* h_im = (const float*)d_in[base + 6];
    const float* n_re = (const float*)d_in[base + 7];
    const float* n_im = (const float*)d_in[base + 8];
    float* out = (float*)d_out;

    const int T = 256;
    zero_c2v_kernel<<<(NEDGE * NCW + T - 1) / T, T>>>();
    setup_csr_kernel<<<1, 1024>>>(cn, vn);
    bits_kernel<<<(NCW * KK + T - 1) / T, T>>>(b, out);
    parity_kernel<<<(NCW * MM + T - 1) / T, T>>>(vn);
    map_kernel<<<(NCW * NSYM + T - 1) / T, T>>>();
    lmmse_kernel<<<(NROW + T - 1) / T, T>>>(h_re, h_im, n_re, n_im, ebno);

    for (int it = 0; it < NITER; it++) {
        var_update_kernel<<<(NN * NCW + T - 1) / T, T>>>();
        check_update_kernel<<<(MM * NCW + T - 1) / T, T>>>(vn);
    }
    var_update_kernel<<<(NN * NCW + T - 1) / T, T>>>();
    bhat_kernel<<<(NCW * KK + T - 1) / T, T>>>(out);
}

// round 9
// speedup vs baseline: 1.3872x; 1.3872x over previous
#include <cuda_runtime.h>
#include <math.h>

// Problem constants (fixed by the reference)
#define NN      1000      // codeword length
#define KK      500       // info bits
#define MM      500       // parity checks
#define NSYM    250       // NN / BPS
#define NITER   5
#define NCW     4000      // BATCH * NUE  (codewords)
#define NROW    250000    // BATCH * NSYM (LMMSE rows)
#define NPE     1500      // P edges (3 per info var, row-major order)
#define NEDGE   2000
#define RSQRT2  0.70710678118654752f

// ---------------- scratch (device globals; no allocation allowed) -----------
// Structure facts (from reference construction):
//   info var v  (v<KK)  owns edges {3v, 3v+1, 3v+2}   (np.nonzero row order)
//   parity var KK+j     owns edge  {NPE + j}
//   check j's edge list = P-edges with cn==j (ascending e) then identity edge last
__device__ unsigned char g_bits[NN * NCW];           // 4 MB  bits [n][cw]
__device__ float2        g_xf[NROW * 4];             // 8 MB  tx symbols
__device__ float4        g_dem[NROW * 4];            // 16 MB {xr, xi, inv_nv, -}
__device__ float         g_Lch[NN * NCW];            // 16 MB channel LLRs [n][cw]
__device__ float         g_c2v_a[NEDGE * NCW];       // 32 MB c2v ping
__device__ float         g_c2v_b[NEDGE * NCW];       // 32 MB c2v pong
__device__ int           g_coff[MM + 1];             // check CSR offsets
__device__ int           g_cedge[NEDGE];             // edge ids per check (stable order)

// 16-QAM constellation (matches reference POINTS)
__constant__ float2 c_pts[16] = {
    { 0.31622776601683794f,  0.31622776601683794f}, { 0.31622776601683794f,  0.9486832980505138f},
    { 0.9486832980505138f,   0.31622776601683794f}, { 0.9486832980505138f,   0.9486832980505138f},
    { 0.31622776601683794f, -0.31622776601683794f}, { 0.31622776601683794f, -0.9486832980505138f},
    { 0.9486832980505138f,  -0.31622776601683794f}, { 0.9486832980505138f,  -0.9486832980505138f},
    {-0.31622776601683794f,  0.31622776601683794f}, {-0.31622776601683794f,  0.9486832980505138f},
    {-0.9486832980505138f,   0.31622776601683794f}, {-0.9486832980505138f,   0.9486832980505138f},
    {-0.31622776601683794f, -0.31622776601683794f}, {-0.31622776601683794f, -0.9486832980505138f},
    {-0.9486832980505138f,  -0.31622776601683794f}, {-0.9486832980505138f,  -0.9486832980505138f}
};

// ---------------- complex helpers -------------------------------------------
struct C2 { float x, y; };
__device__ __forceinline__ C2 cmul(C2 a, C2 b)  { return { a.x*b.x - a.y*b.y, a.x*b.y + a.y*b.x }; }
__device__ __forceinline__ C2 cmulc(C2 a, C2 b) { return { a.x*b.x + a.y*b.y, a.y*b.x - a.x*b.y }; } // a*conj(b)
__device__ __forceinline__ C2 cadd(C2 a, C2 b)  { return { a.x + b.x, a.y + b.y }; }
__device__ __forceinline__ C2 csub(C2 a, C2 b)  { return { a.x - b.x, a.y - b.y }; }
__device__ __forceinline__ C2 cinv(C2 a) { float s = 1.0f/(a.x*a.x + a.y*a.y); return { a.x*s, -a.y*s }; }

// ---------------- zero c2v ping buffer --------------------------------------
__global__ void zero_kernel() {
    int tid = blockIdx.x * blockDim.x + threadIdx.x;       // NEDGE*NCW/4 float4s
    if (tid < NEDGE * NCW / 4)
        reinterpret_cast<float4*>(g_c2v_a)[tid] = make_float4(0.f, 0.f, 0.f, 0.f);
}

// ---------------- setup: check-side CSR (fast structured build) -------------
__global__ void setup_kernel(const int* __restrict__ cn) {
    __shared__ int scn[NPE];
    __shared__ int cnt[MM];
    __shared__ int coff[MM + 1];
    int t = threadIdx.x;
    for (int e = t; e < NPE; e += blockDim.x) scn[e] = cn[e];
    for (int i = t; i < MM; i += blockDim.x) cnt[i] = 0;
    __syncthreads();
    for (int e = t; e < NPE; e += blockDim.x) atomicAdd(&cnt[scn[e]], 1);
    __syncthreads();
    if (t == 0) {
        int a = 0;
        for (int j = 0; j < MM; j++) { coff[j] = a; a += cnt[j] + 1; }  // +1 identity edge
        coff[MM] = a;
    }
    __syncthreads();
    if (t < MM) {
        int pos = coff[t];
        for (int e = 0; e < NPE; e++)
            if (scn[e] == t) g_cedge[pos++] = e;       // ascending edge id (stable)
        g_cedge[pos] = NPE + t;                        // identity edge last
    }
    for (int i = t; i <= MM; i += blockDim.x) g_coff[i] = coff[i];
}

// ---------------- bits: copy bf to out + transpose to [n][cw] ---------------
__global__ void bits_kernel(const int* __restrict__ b, float* __restrict__ out) {
    __shared__ unsigned char tile[32][33];
    int i0 = blockIdx.x * 32, cw0 = blockIdx.y * 32;
    int tx = threadIdx.x, ty = threadIdx.y;                // block (32,8)
    for (int yy = ty; yy < 32; yy += 8) {
        int cw = cw0 + yy, i = i0 + tx;
        if (cw < NCW && i < KK) {
            int v = b[cw * KK + i];
            out[cw * KK + i] = (float)v;                   // bf half of output (exact)
            tile[yy][tx] = (unsigned char)v;
        }
    }
    __syncthreads();
    for (int yy = ty; yy < 32; yy += 8) {
        int i = i0 + yy, cw = cw0 + tx;
        if (cw < NCW && i < KK) g_bits[i * NCW + cw] = tile[tx][yy];
    }
}

// ---------------- parity: XOR over check's P-edges (exact int math) ---------
__global__ void parity_kernel() {
    int tid = blockIdx.x * blockDim.x + threadIdx.x;       // j*NCW + cw
    if (tid >= MM * NCW) return;
    int j = tid / NCW, cw = tid % NCW;
    int b0 = g_coff[j], b1 = g_coff[j + 1] - 1;            // exclude identity edge
    unsigned int acc = 0;
    for (int k = b0; k < b1; k++) {
        int e = g_cedge[k];
        acc ^= g_bits[(e / 3) * NCW + cw];
    }
    g_bits[(KK + j) * NCW + cw] = (unsigned char)(acc & 1u);
}

// ---------------- map: 4 bits -> 16QAM symbol --------------------------------
__global__ void map_kernel() {
    int tid = blockIdx.x * blockDim.x + threadIdx.x;       // s*NCW + cw
    if (tid >= NSYM * NCW) return;
    int s = tid / NCW, cw = tid % NCW;
    int bb = cw >> 2, u = cw & 3;
    int n0 = s * 4;
    int idx = (g_bits[n0 * NCW + cw] << 3) | (g_bits[(n0 + 1) * NCW + cw] << 2)
            | (g_bits[(n0 + 2) * NCW + cw] << 1) |  g_bits[(n0 + 3) * NCW + cw];
    g_xf[(bb * NSYM + s) * 4 + u] = c_pts[idx];
}

// ---------------- LMMSE detect (identical math; compact coalesced output) ---
__global__ void lmmse_kernel(const float* __restrict__ h_re, const float* __restrict__ h_im,
                             const float* __restrict__ n_re, const float* __restrict__ n_im,
                             const float* __restrict__ ebno) {
    int r = blockIdx.x * blockDim.x + threadIdx.x;
    if (r >= NROW) return;

    float no  = 1.0f / (exp10f(ebno[0] * 0.1f) * 4.0f * 0.5f);
    float wsc = sqrtf(no * 0.5f);

    C2 h[4][4];
    const float* hr = h_re + (size_t)r * 16;
    const float* hi = h_im + (size_t)r * 16;
#pragma unroll
    for (int i = 0; i < 4; i++)
#pragma unroll
        for (int j = 0; j < 4; j++)
            h[i][j] = { hr[i*4 + j] * RSQRT2, hi[i*4 + j] * RSQRT2 };

    C2 y[4];
#pragma unroll
    for (int i = 0; i < 4; i++) {
        C2 acc = { n_re[r*4 + i] * wsc, n_im[r*4 + i] * wsc };
#pragma unroll
        for (int j = 0; j < 4; j++) {
            float2 xj = g_xf[r*4 + j];
            acc = cadd(acc, cmul(h[i][j], {xj.x, xj.y}));
        }
        y[i] = acc;
    }

    // augmented [A | y | h], A = h h^H + no I
    C2 Mx[4][9];
#pragma unroll
    for (int i = 0; i < 4; i++) {
#pragma unroll
        for (int k = 0; k < 4; k++) {
            C2 a = { (i == k) ? no : 0.0f, 0.0f };
#pragma unroll
            for (int j = 0; j < 4; j++) a = cadd(a, cmulc(h[i][j], h[k][j]));
            Mx[i][k] = a;
        }
        Mx[i][4] = y[i];
#pragma unroll
        for (int j = 0; j < 4; j++) Mx[i][5 + j] = h[i][j];
    }

    // LU with partial pivoting (LAPACK cabs1 = |re|+|im|)
#pragma unroll
    for (int k = 0; k < 4; k++) {
        int p = k;
        float best = fabsf(Mx[k][k].x) + fabsf(Mx[k][k].y);
#pragma unroll
        for (int q = k + 1; q < 4; q++) {
            float m = fabsf(Mx[q][k].x) + fabsf(Mx[q][k].y);
            if (m > best) { best = m; p = q; }
        }
        if (p != k) {
#pragma unroll
            for (int c = 0; c < 9; c++) { C2 tmp = Mx[k][c]; Mx[k][c] = Mx[p][c]; Mx[p][c] = tmp; }
        }
        C2 piv_inv = cinv(Mx[k][k]);
#pragma unroll
        for (int rr = k + 1; rr < 4; rr++) {
            C2 f = cmul(Mx[rr][k], piv_inv);
#pragma unroll
            for (int c = k + 1; c < 9; c++) Mx[rr][c] = csub(Mx[rr][c], cmul(f, Mx[k][c]));
        }
    }
    C2 dinv[4];
#pragma unroll
    for (int i = 0; i < 4; i++) dinv[i] = cinv(Mx[i][i]);
#pragma unroll
    for (int c = 4; c < 9; c++) {
#pragma unroll
        for (int rr = 3; rr >= 0; rr--) {
            C2 val = Mx[rr][c];
#pragma unroll
            for (int q = 0; q < 4; q++)
                if (q > rr) val = csub(val, cmul(Mx[rr][q], Mx[q][c]));
            Mx[rr][c] = cmul(val, dinv[rr]);
        }
    }

#pragma unroll
    for (int j = 0; j < 4; j++) {
        C2 xraw = {0.f, 0.f};
        float d = 0.f;
#pragma unroll
        for (int i = 0; i < 4; i++) {
            xraw = cadd(xraw, cmulc(Mx[i][4], h[i][j]));
            C2 gw = cmulc(Mx[i][5 + j], h[i][j]);
            d += gw.x;
        }
        float inv_d = 1.0f / d;
        float xr = xraw.x * inv_d, xi = xraw.y * inv_d;
        float noe = fmaxf(inv_d - 1.0f, 1e-12f);
        float inv_nv = 1.0f / noe;
        g_dem[r * 4 + j] = make_float4(xr, xi, inv_nv, 0.0f);
    }
}

// ---------------- max-log demap (identical expressions; coalesced writes) ---
__global__ void demap_kernel() {
    int tid = blockIdx.x * blockDim.x + threadIdx.x;       // s*NCW + cw
    if (tid >= NSYM * NCW) return;
    int s = tid / NCW, cw = tid % NCW;
    int bb = cw >> 2, u = cw & 3;
    float4 dm = g_dem[(bb * NSYM + s) * 4 + u];
    float xr = dm.x, xi = dm.y, inv_nv = dm.z;

    float best0[4] = {3.4e38f, 3.4e38f, 3.4e38f, 3.4e38f};
    float best1[4] = {3.4e38f, 3.4e38f, 3.4e38f, 3.4e38f};
#pragma unroll
    for (int p = 0; p < 16; p++) {
        float dr = xr - c_pts[p].x, di = xi - c_pts[p].y;
        float d2 = dr * dr + di * di;
#pragma unroll
        for (int k = 0; k < 4; k++) {
            if ((p >> (3 - k)) & 1) best1[k] = fminf(best1[k], d2);
            else                    best0[k] = fminf(best0[k], d2);
        }
    }
#pragma unroll
    for (int k = 0; k < 4; k++)
        g_Lch[(size_t)(s * 4 + k) * NCW + cw] = (best1[k] - best0[k]) * inv_nv;
}

// ---------------- fused LDPC iteration (vtot inline, double-buffered) -------
__device__ __forceinline__ float tanh_clamped(float m) {
    float a = fminf(fmaxf(0.5f * m, -9.9f), 9.9f);
    float t = tanhf(a);
    return (t >= 0.0f) ? fmaxf(t, 1e-7f) : fminf(t, -1e-7f);
}

// m_vc for edge e seen from its variable, given old c2v (order matches R1 var pass)
__device__ __forceinline__ float edge_msg(const float* __restrict__ o, int e, int cw) {
    if (e < NPE) {
        int v = e / 3, r0 = v * 3;
        float a0 = o[r0 * NCW + cw];
        float a1 = o[(r0 + 1) * NCW + cw];
        float a2 = o[(r0 + 2) * NCW + cw];
        float vt = ((g_Lch[v * NCW + cw] + a0) + a1) + a2;     // ascending edge order
        int sl = e - r0;
        float me = (sl == 0) ? a0 : ((sl == 1) ? a1 : a2);
        return vt - me;
    } else {
        int v = KK + (e - NPE);
        float cc = o[e * NCW + cw];
        float vt = g_Lch[v * NCW + cw] + cc;
        return vt - cc;                                        // keep (L+c)-c rounding
    }
}

// DIR=0: read g_c2v_a, write g_c2v_b.  DIR=1: read g_c2v_b, write g_c2v_a.
template <int DIR>
__global__ void ldpc_iter_kernel() {
    const float* __restrict__ o = DIR ? g_c2v_b : g_c2v_a;
    float* __restrict__ n       = DIR ? g_c2v_a : g_c2v_b;
    int tid = blockIdx.x * blockDim.x + threadIdx.x;           // j*NCW + cw
    if (tid >= MM * NCW) return;
    int j = tid / NCW, cw = tid % NCW;
    int b0 = g_coff[j], b1 = g_coff[j + 1];
    float prod = 1.0f;
    for (int k = b0; k < b1; k++)
        prod *= tanh_clamped(edge_msg(o, g_cedge[k], cw));
    for (int k = b0; k < b1; k++) {
        int e = g_cedge[k];
        float t = tanh_clamped(edge_msg(o, e, cw));            // recompute (L1-hot)
        float ratio = prod / t;
        ratio = fminf(fmaxf(ratio, -0.999999f), 0.999999f);
        n[e * NCW + cw] = 2.0f * atanhf(ratio);
    }
}

// ---------------- final hard decision + transposed write --------------------
// Reads g_c2v_b (final messages after 5 iterations: a->b,b->a,a->b,b->a,a->b)
__global__ void bhat_kernel(float* __restrict__ out) {
    __shared__ float tile[32][33];
    int i0 = blockIdx.x * 32, cw0 = blockIdx.y * 32;
    int tx = threadIdx.x, ty = threadIdx.y;                    // block (32,8)
    for (int yy = ty; yy < 32; yy += 8) {
        int i = i0 + yy, cw = cw0 + tx;
        if (cw < NCW && i < KK) {
            int r0 = i * 3;
            float s = g_Lch[i * NCW + cw];
            s += g_c2v_b[r0 * NCW + cw];
            s += g_c2v_b[(r0 + 1) * NCW + cw];
            s += g_c2v_b[(r0 + 2) * NCW + cw];
            tile[yy][tx] = (s < 0.0f) ? 1.0f : 0.0f;
        }
    }
    __syncthreads();
    for (int yy = ty; yy < 32; yy += 8) {
        int cw = cw0 + yy, i = i0 + tx;
        if (cw < NCW && i < KK)
            out[(size_t)NCW * KK + (size_t)cw * KK + i] = tile[tx][yy];
    }
}

// ---------------- launch ----------------------------------------------------
extern "C" void kernel_launch(void* const* d_in, const int* in_sizes, int n_in,
                              void* d_out, int out_size) {
    int base = n_in - 9;
    const float* ebno = (const float*)d_in[base + 0];
    const int*   b    = (const int*)  d_in[base + 1];
    const int*   cn   = (const int*)  d_in[base + 3];
    const float* h_re = (const float*)d_in[base + 5];
    const float* h_im = (const float*)d_in[base + 6];
    const float* n_re = (const float*)d_in[base + 7];
    const float* n_im = (const float*)d_in[base + 8];
    float* out = (float*)d_out;

    const int T = 256;

    zero_kernel<<<(NEDGE * NCW / 4 + T - 1) / T, T>>>();
    setup_kernel<<<1, 512>>>(cn);

    dim3 tb(32, 8);
    bits_kernel<<<dim3((KK + 31) / 32, NCW / 32), tb>>>(b, out);
    parity_kernel<<<(MM * NCW + T - 1) / T, T>>>();
    map_kernel<<<(NSYM * NCW + T - 1) / T, T>>>();
    lmmse_kernel<<<(NROW + T - 1) / T, T>>>(h_re, h_im, n_re, n_im, ebno);
    demap_kernel<<<(NSYM * NCW + T - 1) / T, T>>>();

    // 5 fused iterations, ping-pong via template direction (a starts zeroed)
    const int G = (MM * NCW + T - 1) / T;
    ldpc_iter_kernel<0><<<G, T>>>();   // a -> b
    ldpc_iter_kernel<1><<<G, T>>>();   // b -> a
    ldpc_iter_kernel<0><<<G, T>>>();   // a -> b
    ldpc_iter_kernel<1><<<G, T>>>();   // b -> a
    ldpc_iter_kernel<0><<<G, T>>>();   // a -> b  (final in g_c2v_b)

    bhat_kernel<<<dim3((KK + 31) / 32, NCW / 32), tb>>>(out);
}

// round 10
// speedup vs baseline: 1.4170x; 1.0215x over previous
#include <cuda_runtime.h>
#include <math.h>

// Problem constants (fixed by the reference)
#define NN      1000      // codeword length
#define KK      500       // info bits
#define MM      500       // parity checks
#define NSYM    250       // NN / BPS
#define NITER   5
#define NCW     4000      // BATCH * NUE  (codewords)
#define NROW    250000    // BATCH * NSYM (LMMSE rows)
#define NPE     1500      // P edges (3 per info var, row-major order)
#define NEDGE   2000
#define MAXDEG  16        // max check degree handled in registers (deg = cnt+1)
#define RSQRT2  0.70710678118654752f

// ---------------- scratch (device globals; no allocation allowed) -----------
// Structure facts (from reference construction):
//   info var v  (v<KK)  owns edges {3v, 3v+1, 3v+2}   (np.nonzero row order)
//   parity var KK+j     owns edge  {NPE + j}
//   check j's edge list = P-edges with cn==j (ascending e) then identity edge last
__device__ unsigned char g_bits[NN * NCW];           // 4 MB  bits [n][cw]
__device__ float2        g_xf[NROW * 4];             // 8 MB  tx symbols
__device__ float4        g_dem[NROW * 4];            // 16 MB {xr, xi, inv_nv, -}
__device__ float         g_Lch[NN * NCW];            // 16 MB channel LLRs [n][cw]
__device__ float         g_c2v_a[NEDGE * NCW];       // 32 MB c2v ping
__device__ float         g_c2v_b[NEDGE * NCW];       // 32 MB c2v pong
__device__ int           g_coff[MM + 1];             // check CSR offsets
__device__ int           g_cedge[NEDGE];             // edge ids per check (stable order)

// 16-QAM constellation (matches reference POINTS)
__constant__ float2 c_pts[16] = {
    { 0.31622776601683794f,  0.31622776601683794f}, { 0.31622776601683794f,  0.9486832980505138f},
    { 0.9486832980505138f,   0.31622776601683794f}, { 0.9486832980505138f,   0.9486832980505138f},
    { 0.31622776601683794f, -0.31622776601683794f}, { 0.31622776601683794f, -0.9486832980505138f},
    { 0.9486832980505138f,  -0.31622776601683794f}, { 0.9486832980505138f,  -0.9486832980505138f},
    {-0.31622776601683794f,  0.31622776601683794f}, {-0.31622776601683794f,  0.9486832980505138f},
    {-0.9486832980505138f,   0.31622776601683794f}, {-0.9486832980505138f,   0.9486832980505138f},
    {-0.31622776601683794f, -0.31622776601683794f}, {-0.31622776601683794f, -0.9486832980505138f},
    {-0.9486832980505138f,  -0.31622776601683794f}, {-0.9486832980505138f,  -0.9486832980505138f}
};

// ---------------- complex helpers -------------------------------------------
struct C2 { float x, y; };
__device__ __forceinline__ C2 cmul(C2 a, C2 b)  { return { a.x*b.x - a.y*b.y, a.x*b.y + a.y*b.x }; }
__device__ __forceinline__ C2 cmulc(C2 a, C2 b) { return { a.x*b.x + a.y*b.y, a.y*b.x - a.x*b.y }; } // a*conj(b)
__device__ __forceinline__ C2 cadd(C2 a, C2 b)  { return { a.x + b.x, a.y + b.y }; }
__device__ __forceinline__ C2 csub(C2 a, C2 b)  { return { a.x - b.x, a.y - b.y }; }
__device__ __forceinline__ C2 cinv(C2 a) { float s = 1.0f/(a.x*a.x + a.y*a.y); return { a.x*s, -a.y*s }; }

// ---------------- zero c2v ping buffer --------------------------------------
__global__ void zero_kernel() {
    int tid = blockIdx.x * blockDim.x + threadIdx.x;       // NEDGE*NCW/4 float4s
    if (tid < NEDGE * NCW / 4)
        reinterpret_cast<float4*>(g_c2v_a)[tid] = make_float4(0.f, 0.f, 0.f, 0.f);
}

// ---------------- setup: check-side CSR (fast structured build) -------------
__global__ void setup_kernel(const int* __restrict__ cn) {
    __shared__ int scn[NPE];
    __shared__ int cnt[MM];
    __shared__ int coff[MM + 1];
    int t = threadIdx.x;
    for (int e = t; e < NPE; e += blockDim.x) scn[e] = cn[e];
    for (int i = t; i < MM; i += blockDim.x) cnt[i] = 0;
    __syncthreads();
    for (int e = t; e < NPE; e += blockDim.x) atomicAdd(&cnt[scn[e]], 1);
    __syncthreads();
    if (t == 0) {
        int a = 0;
        for (int j = 0; j < MM; j++) { coff[j] = a; a += cnt[j] + 1; }  // +1 identity edge
        coff[MM] = a;
    }
    __syncthreads();
    if (t < MM) {
        int pos = coff[t];
        for (int e = 0; e < NPE; e++)
            if (scn[e] == t) g_cedge[pos++] = e;       // ascending edge id (stable)
        g_cedge[pos] = NPE + t;                        // identity edge last
    }
    for (int i = t; i <= MM; i += blockDim.x) g_coff[i] = coff[i];
}

// ---------------- bits: copy bf to out + transpose to [n][cw] ---------------
__global__ void bits_kernel(const int* __restrict__ b, float* __restrict__ out) {
    __shared__ unsigned char tile[32][33];
    int i0 = blockIdx.x * 32, cw0 = blockIdx.y * 32;
    int tx = threadIdx.x, ty = threadIdx.y;                // block (32,8)
    for (int yy = ty; yy < 32; yy += 8) {
        int cw = cw0 + yy, i = i0 + tx;
        if (cw < NCW && i < KK) {
            int v = b[cw * KK + i];
            out[cw * KK + i] = (float)v;                   // bf half of output (exact)
            tile[yy][tx] = (unsigned char)v;
        }
    }
    __syncthreads();
    for (int yy = ty; yy < 32; yy += 8) {
        int i = i0 + yy, cw = cw0 + tx;
        if (cw < NCW && i < KK) g_bits[i * NCW + cw] = tile[tx][yy];
    }
}

// ---------------- parity: XOR over check's P-edges (4 cw per thread) --------
__global__ void parity_kernel() {
    int tid = blockIdx.x * blockDim.x + threadIdx.x;       // j*(NCW/4) + cw4
    if (tid >= MM * (NCW / 4)) return;
    int j = tid / (NCW / 4), cw4 = tid % (NCW / 4);
    int b0 = g_coff[j], b1 = g_coff[j + 1] - 1;            // exclude identity edge
    unsigned int acc = 0;
    for (int k = b0; k < b1; k++) {
        int e = g_cedge[k];
        acc ^= *reinterpret_cast<const unsigned int*>(&g_bits[(e / 3) * NCW + cw4 * 4]);
    }
    *reinterpret_cast<unsigned int*>(&g_bits[(KK + j) * NCW + cw4 * 4]) = acc & 0x01010101u;
}

// ---------------- map: 4 bits -> 16QAM symbol (4 cw per thread) --------------
__global__ void map_kernel() {
    int tid = blockIdx.x * blockDim.x + threadIdx.x;       // s*(NCW/4) + cw4
    if (tid >= NSYM * (NCW / 4)) return;
    int s = tid / (NCW / 4), cw4 = tid % (NCW / 4);        // bb = cw>>2 = cw4, u = cw&3
    int n0 = s * 4;
    uchar4 r0 = *reinterpret_cast<const uchar4*>(&g_bits[ n0      * NCW + cw4 * 4]);
    uchar4 r1 = *reinterpret_cast<const uchar4*>(&g_bits[(n0 + 1) * NCW + cw4 * 4]);
    uchar4 r2 = *reinterpret_cast<const uchar4*>(&g_bits[(n0 + 2) * NCW + cw4 * 4]);
    uchar4 r3 = *reinterpret_cast<const uchar4*>(&g_bits[(n0 + 3) * NCW + cw4 * 4]);
    float2* dst = &g_xf[((size_t)cw4 * NSYM + s) * 4];
    dst[0] = c_pts[(r0.x << 3) | (r1.x << 2) | (r2.x << 1) | r3.x];
    dst[1] = c_pts[(r0.y << 3) | (r1.y << 2) | (r2.y << 1) | r3.y];
    dst[2] = c_pts[(r0.z << 3) | (r1.z << 2) | (r2.z << 1) | r3.z];
    dst[3] = c_pts[(r0.w << 3) | (r1.w << 2) | (r2.w << 1) | r3.w];
}

// ---------------- LMMSE detect (identical math; compact coalesced output) ---
__global__ void lmmse_kernel(const float* __restrict__ h_re, const float* __restrict__ h_im,
                             const float* __restrict__ n_re, const float* __restrict__ n_im,
                             const float* __restrict__ ebno) {
    int r = blockIdx.x * blockDim.x + threadIdx.x;
    if (r >= NROW) return;

    float no  = 1.0f / (exp10f(ebno[0] * 0.1f) * 4.0f * 0.5f);
    float wsc = sqrtf(no * 0.5f);

    C2 h[4][4];
    const float* hr = h_re + (size_t)r * 16;
    const float* hi = h_im + (size_t)r * 16;
#pragma unroll
    for (int i = 0; i < 4; i++)
#pragma unroll
        for (int j = 0; j < 4; j++)
            h[i][j] = { hr[i*4 + j] * RSQRT2, hi[i*4 + j] * RSQRT2 };

    C2 y[4];
#pragma unroll
    for (int i = 0; i < 4; i++) {
        C2 acc = { n_re[r*4 + i] * wsc, n_im[r*4 + i] * wsc };
#pragma unroll
        for (int j = 0; j < 4; j++) {
            float2 xj = g_xf[r*4 + j];
            acc = cadd(acc, cmul(h[i][j], {xj.x, xj.y}));
        }
        y[i] = acc;
    }

    // augmented [A | y | h], A = h h^H + no I
    C2 Mx[4][9];
#pragma unroll
    for (int i = 0; i < 4; i++) {
#pragma unroll
        for (int k = 0; k < 4; k++) {
            C2 a = { (i == k) ? no : 0.0f, 0.0f };
#pragma unroll
            for (int j = 0; j < 4; j++) a = cadd(a, cmulc(h[i][j], h[k][j]));
            Mx[i][k] = a;
        }
        Mx[i][4] = y[i];
#pragma unroll
        for (int j = 0; j < 4; j++) Mx[i][5 + j] = h[i][j];
    }

    // LU with partial pivoting (LAPACK cabs1 = |re|+|im|)
#pragma unroll
    for (int k = 0; k < 4; k++) {
        int p = k;
        float best = fabsf(Mx[k][k].x) + fabsf(Mx[k][k].y);
#pragma unroll
        for (int q = k + 1; q < 4; q++) {
            float m = fabsf(Mx[q][k].x) + fabsf(Mx[q][k].y);
            if (m > best) { best = m; p = q; }
        }
        if (p != k) {
#pragma unroll
            for (int c = 0; c < 9; c++) { C2 tmp = Mx[k][c]; Mx[k][c] = Mx[p][c]; Mx[p][c] = tmp; }
        }
        C2 piv_inv = cinv(Mx[k][k]);
#pragma unroll
        for (int rr = k + 1; rr < 4; rr++) {
            C2 f = cmul(Mx[rr][k], piv_inv);
#pragma unroll
            for (int c = k + 1; c < 9; c++) Mx[rr][c] = csub(Mx[rr][c], cmul(f, Mx[k][c]));
        }
    }
    C2 dinv[4];
#pragma unroll
    for (int i = 0; i < 4; i++) dinv[i] = cinv(Mx[i][i]);
#pragma unroll
    for (int c = 4; c < 9; c++) {
#pragma unroll
        for (int rr = 3; rr >= 0; rr--) {
            C2 val = Mx[rr][c];
#pragma unroll
            for (int q = 0; q < 4; q++)
                if (q > rr) val = csub(val, cmul(Mx[rr][q], Mx[q][c]));
            Mx[rr][c] = cmul(val, dinv[rr]);
        }
    }

#pragma unroll
    for (int j = 0; j < 4; j++) {
        C2 xraw = {0.f, 0.f};
        float d = 0.f;
#pragma unroll
        for (int i = 0; i < 4; i++) {
            xraw = cadd(xraw, cmulc(Mx[i][4], h[i][j]));
            C2 gw = cmulc(Mx[i][5 + j], h[i][j]);
            d += gw.x;
        }
        float inv_d = 1.0f / d;
        float xr = xraw.x * inv_d, xi = xraw.y * inv_d;
        float noe = fmaxf(inv_d - 1.0f, 1e-12f);
        float inv_nv = 1.0f / noe;
        g_dem[r * 4 + j] = make_float4(xr, xi, inv_nv, 0.0f);
    }
}

// ---------------- max-log demap (identical expressions; coalesced writes) ---
__global__ void demap_kernel() {
    int tid = blockIdx.x * blockDim.x + threadIdx.x;       // s*NCW + cw
    if (tid >= NSYM * NCW) return;
    int s = tid / NCW, cw = tid % NCW;
    int bb = cw >> 2, u = cw & 3;
    float4 dm = g_dem[(bb * NSYM + s) * 4 + u];
    float xr = dm.x, xi = dm.y, inv_nv = dm.z;

    float best0[4] = {3.4e38f, 3.4e38f, 3.4e38f, 3.4e38f};
    float best1[4] = {3.4e38f, 3.4e38f, 3.4e38f, 3.4e38f};
#pragma unroll
    for (int p = 0; p < 16; p++) {
        float dr = xr - c_pts[p].x, di = xi - c_pts[p].y;
        float d2 = dr * dr + di * di;
#pragma unroll
        for (int k = 0; k < 4; k++) {
            if ((p >> (3 - k)) & 1) best1[k] = fminf(best1[k], d2);
            else                    best0[k] = fminf(best0[k], d2);
        }
    }
#pragma unroll
    for (int k = 0; k < 4; k++)
        g_Lch[(size_t)(s * 4 + k) * NCW + cw] = (best1[k] - best0[k]) * inv_nv;
}

// ---------------- fused LDPC iteration (vtot inline, double-buffered) -------
__device__ __forceinline__ float tanh_clamped(float m) {
    float a = fminf(fmaxf(0.5f * m, -9.9f), 9.9f);
    float t = tanhf(a);
    return (t >= 0.0f) ? fmaxf(t, 1e-7f) : fminf(t, -1e-7f);
}

// m_vc for edge e seen from its variable, given old c2v (order matches R1 var pass)
__device__ __forceinline__ float edge_msg(const float* __restrict__ o, int e, int cw) {
    if (e < NPE) {
        int v = e / 3, r0 = v * 3;
        float a0 = o[r0 * NCW + cw];
        float a1 = o[(r0 + 1) * NCW + cw];
        float a2 = o[(r0 + 2) * NCW + cw];
        float vt = ((g_Lch[v * NCW + cw] + a0) + a1) + a2;     // ascending edge order
        int sl = e - r0;
        float me = (sl == 0) ? a0 : ((sl == 1) ? a1 : a2);
        return vt - me;
    } else {
        int v = KK + (e - NPE);
        float cc = o[e * NCW + cw];
        float vt = g_Lch[v * NCW + cw] + cc;
        return vt - cc;                                        // keep (L+c)-c rounding
    }
}

// DIR=0: read g_c2v_a, write g_c2v_b.  DIR=1: read g_c2v_b, write g_c2v_a.
// Pass-1 tanh values are kept in a fully-unrolled register array; pass 2 only
// does prod/t + atanh (identical fp values/order to the two-pass recompute).
template <int DIR>
__global__ void ldpc_iter_kernel() {
    const float* __restrict__ o = DIR ? g_c2v_b : g_c2v_a;
    float* __restrict__ n       = DIR ? g_c2v_a : g_c2v_b;
    int tid = blockIdx.x * blockDim.x + threadIdx.x;           // j*NCW + cw
    if (tid >= MM * NCW) return;
    int j = tid / NCW, cw = tid % NCW;
    int b0 = g_coff[j], b1 = g_coff[j + 1];
    int deg = b1 - b0;

    if (deg <= MAXDEG) {
        float t[MAXDEG];
        float prod = 1.0f;
#pragma unroll
        for (int k = 0; k < MAXDEG; k++) {
            if (k < deg) {
                float tt = tanh_clamped(edge_msg(o, g_cedge[b0 + k], cw));
                t[k] = tt;
                prod *= tt;
            }
        }
#pragma unroll
        for (int k = 0; k < MAXDEG; k++) {
            if (k < deg) {
                float ratio = prod / t[k];
                ratio = fminf(fmaxf(ratio, -0.999999f), 0.999999f);
                n[g_cedge[b0 + k] * NCW + cw] = 2.0f * atanhf(ratio);
            }
        }
    } else {
        // fallback (degree beyond register cache; identical math, recompute)
        float prod = 1.0f;
        for (int k = b0; k < b1; k++)
            prod *= tanh_clamped(edge_msg(o, g_cedge[k], cw));
        for (int k = b0; k < b1; k++) {
            int e = g_cedge[k];
            float tt = tanh_clamped(edge_msg(o, e, cw));
            float ratio = prod / tt;
            ratio = fminf(fmaxf(ratio, -0.999999f), 0.999999f);
            n[e * NCW + cw] = 2.0f * atanhf(ratio);
        }
    }
}

// ---------------- final hard decision + transposed write --------------------
// Reads g_c2v_b (final messages after 5 iterations: a->b,b->a,a->b,b->a,a->b)
__global__ void bhat_kernel(float* __restrict__ out) {
    __shared__ float tile[32][33];
    int i0 = blockIdx.x * 32, cw0 = blockIdx.y * 32;
    int tx = threadIdx.x, ty = threadIdx.y;                    // block (32,8)
    for (int yy = ty; yy < 32; yy += 8) {
        int i = i0 + yy, cw = cw0 + tx;
        if (cw < NCW && i < KK) {
            int r0 = i * 3;
            float s = g_Lch[i * NCW + cw];
            s += g_c2v_b[r0 * NCW + cw];
            s += g_c2v_b[(r0 + 1) * NCW + cw];
            s += g_c2v_b[(r0 + 2) * NCW + cw];
            tile[yy][tx] = (s < 0.0f) ? 1.0f : 0.0f;
        }
    }
    __syncthreads();
    for (int yy = ty; yy < 32; yy += 8) {
        int cw = cw0 + yy, i = i0 + tx;
        if (cw < NCW && i < KK)
            out[(size_t)NCW * KK + (size_t)cw * KK + i] = tile[tx][yy];
    }
}

// ---------------- launch ----------------------------------------------------
extern "C" void kernel_launch(void* const* d_in, const int* in_sizes, int n_in,
                              void* d_out, int out_size) {
    int base = n_in - 9;
    const float* ebno = (const float*)d_in[base + 0];
    const int*   b    = (const int*)  d_in[base + 1];
    const int*   cn   = (const int*)  d_in[base + 3];
    const float* h_re = (const float*)d_in[base + 5];
    const float* h_im = (const float*)d_in[base + 6];
    const float* n_re = (const float*)d_in[base + 7];
    const float* n_im = (const float*)d_in[base + 8];
    float* out = (float*)d_out;

    const int T = 256;

    zero_kernel<<<(NEDGE * NCW / 4 + T - 1) / T, T>>>();
    setup_kernel<<<1, 512>>>(cn);

    dim3 tb(32, 8);
    bits_kernel<<<dim3((KK + 31) / 32, NCW / 32), tb>>>(b, out);
    parity_kernel<<<(MM * (NCW / 4) + T - 1) / T, T>>>();
    map_kernel<<<(NSYM * (NCW / 4) + T - 1) / T, T>>>();
    lmmse_kernel<<<(NROW + T - 1) / T, T>>>(h_re, h_im, n_re, n_im, ebno);
    demap_kernel<<<(NSYM * NCW + T - 1) / T, T>>>();

    // 5 fused iterations, ping-pong via template direction (a starts zeroed)
    const int G = (MM * NCW + T - 1) / T;
    ldpc_iter_kernel<0><<<G, T>>>();   // a -> b
    ldpc_iter_kernel<1><<<G, T>>>();   // b -> a
    ldpc_iter_kernel<0><<<G, T>>>();   // a -> b
    ldpc_iter_kernel<1><<<G, T>>>();   // b -> a
    ldpc_iter_kernel<0><<<G, T>>>();   // a -> b  (final in g_c2v_b)

    bhat_kernel<<<dim3((KK + 31) / 32, NCW / 32), tb>>>(out);
}

// round 12
// speedup vs baseline: 1.9431x; 1.3713x over previous
#include <cuda_runtime.h>
#include <math.h>

// Problem constants (fixed by the reference)
#define NN      1000      // codeword length
#define KK      500       // info bits
#define MM      500       // parity checks
#define NSYM    250       // NN / BPS
#define NITER   5
#define NCW     4000      // BATCH * NUE  (codewords)
#define NROW    250000    // BATCH * NSYM (LMMSE rows)
#define NPE     1500      // P edges (3 per info var, row-major order)
#define NEDGE   2000
#define MAXDEG  12        // max check degree handled in registers
#define RSQRT2  0.70710678118654752f

// ---------------- scratch (device globals; no allocation allowed) -----------
__device__ unsigned char g_bits[NN * NCW];           // 4 MB  bits [n][cw]
__device__ float2        g_xf[NROW * 4];             // 8 MB  tx symbols
__device__ float4        g_dem[NROW * 4];            // 16 MB {xr, xi, inv_nv, -}
__device__ float         g_Lch[NN * NCW];            // 16 MB channel LLRs [n][cw]
__device__ float         g_c2v_a[NEDGE * NCW];       // 32 MB c2v ping
__device__ float         g_c2v_b[NEDGE * NCW];       // 32 MB c2v pong
__device__ int           g_coff[MM + 1];             // check CSR offsets
__device__ int           g_cedge[NEDGE];             // edge ids per check (stable order)

// 16-QAM constellation (matches reference POINTS)
__constant__ float2 c_pts[16] = {
    { 0.31622776601683794f,  0.31622776601683794f}, { 0.31622776601683794f,  0.9486832980505138f},
    { 0.9486832980505138f,   0.31622776601683794f}, { 0.9486832980505138f,   0.9486832980505138f},
    { 0.31622776601683794f, -0.31622776601683794f}, { 0.31622776601683794f, -0.9486832980505138f},
    { 0.9486832980505138f,  -0.31622776601683794f}, { 0.9486832980505138f,  -0.9486832980505138f},
    {-0.31622776601683794f,  0.31622776601683794f}, {-0.31622776601683794f,  0.9486832980505138f},
    {-0.9486832980505138f,   0.31622776601683794f}, {-0.9486832980505138f,   0.9486832980505138f},
    {-0.31622776601683794f, -0.31622776601683794f}, {-0.31622776601683794f, -0.9486832980505138f},
    {-0.9486832980505138f,  -0.31622776601683794f}, {-0.9486832980505138f,  -0.9486832980505138f}
};

// ---------------- complex helpers -------------------------------------------
struct C2 { float x, y; };
__device__ __forceinline__ C2 cmul(C2 a, C2 b)  { return { a.x*b.x - a.y*b.y, a.x*b.y + a.y*b.x }; }
__device__ __forceinline__ C2 cmulc(C2 a, C2 b) { return { a.x*b.x + a.y*b.y, a.y*b.x - a.x*b.y }; } // a*conj(b)
__device__ __forceinline__ C2 cadd(C2 a, C2 b)  { return { a.x + b.x, a.y + b.y }; }
__device__ __forceinline__ C2 csub(C2 a, C2 b)  { return { a.x - b.x, a.y - b.y }; }
__device__ __forceinline__ C2 cinv(C2 a) { float s = 1.0f/(a.x*a.x + a.y*a.y); return { a.x*s, -a.y*s }; }

// ---------------- zero c2v ping buffer --------------------------------------
__global__ void zero_kernel() {
    int tid = blockIdx.x * blockDim.x + threadIdx.x;
    if (tid < NEDGE * NCW / 4)
        reinterpret_cast<float4*>(g_c2v_a)[tid] = make_float4(0.f, 0.f, 0.f, 0.f);
}

// ---------------- setup: check-side CSR (fast structured build) -------------
__global__ void setup_kernel(const int* __restrict__ cn) {
    __shared__ int scn[NPE];
    __shared__ int cnt[MM];
    __shared__ int coff[MM + 1];
    int t = threadIdx.x;
    for (int e = t; e < NPE; e += blockDim.x) scn[e] = cn[e];
    for (int i = t; i < MM; i += blockDim.x) cnt[i] = 0;
    __syncthreads();
    for (int e = t; e < NPE; e += blockDim.x) atomicAdd(&cnt[scn[e]], 1);
    __syncthreads();
    if (t == 0) {
        int a = 0;
        for (int j = 0; j < MM; j++) { coff[j] = a; a += cnt[j] + 1; }  // +1 identity edge
        coff[MM] = a;
    }
    __syncthreads();
    if (t < MM) {
        int pos = coff[t];
        for (int e = 0; e < NPE; e++)
            if (scn[e] == t) g_cedge[pos++] = e;       // ascending edge id (stable)
        g_cedge[pos] = NPE + t;                        // identity edge last
    }
    for (int i = t; i <= MM; i += blockDim.x) g_coff[i] = coff[i];
}

// ---------------- bits: copy bf to out + transpose to [n][cw] ---------------
__global__ void bits_kernel(const int* __restrict__ b, float* __restrict__ out) {
    __shared__ unsigned char tile[32][33];
    int i0 = blockIdx.x * 32, cw0 = blockIdx.y * 32;
    int tx = threadIdx.x, ty = threadIdx.y;                // block (32,8)
    for (int yy = ty; yy < 32; yy += 8) {
        int cw = cw0 + yy, i = i0 + tx;
        if (cw < NCW && i < KK) {
            int v = b[cw * KK + i];
            out[cw * KK + i] = (float)v;                   // bf half of output (exact)
            tile[yy][tx] = (unsigned char)v;
        }
    }
    __syncthreads();
    for (int yy = ty; yy < 32; yy += 8) {
        int i = i0 + yy, cw = cw0 + tx;
        if (cw < NCW && i < KK) g_bits[i * NCW + cw] = tile[tx][yy];
    }
}

// ---------------- parity: XOR over check's P-edges (4 cw per thread) --------
__global__ void parity_kernel() {
    int tid = blockIdx.x * blockDim.x + threadIdx.x;       // j*(NCW/4) + cw4
    if (tid >= MM * (NCW / 4)) return;
    int j = tid / (NCW / 4), cw4 = tid % (NCW / 4);
    int b0 = g_coff[j], b1 = g_coff[j + 1] - 1;            // exclude identity edge
    unsigned int acc = 0;
    for (int k = b0; k < b1; k++) {
        int e = g_cedge[k];
        acc ^= *reinterpret_cast<const unsigned int*>(&g_bits[(e / 3) * NCW + cw4 * 4]);
    }
    *reinterpret_cast<unsigned int*>(&g_bits[(KK + j) * NCW + cw4 * 4]) = acc & 0x01010101u;
}

// ---------------- map: 4 bits -> 16QAM symbol (4 cw per thread) --------------
__global__ void map_kernel() {
    int tid = blockIdx.x * blockDim.x + threadIdx.x;       // s*(NCW/4) + cw4
    if (tid >= NSYM * (NCW / 4)) return;
    int s = tid / (NCW / 4), cw4 = tid % (NCW / 4);        // bb = cw>>2 = cw4, u = cw&3
    int n0 = s * 4;
    uchar4 r0 = *reinterpret_cast<const uchar4*>(&g_bits[ n0      * NCW + cw4 * 4]);
    uchar4 r1 = *reinterpret_cast<const uchar4*>(&g_bits[(n0 + 1) * NCW + cw4 * 4]);
    uchar4 r2 = *reinterpret_cast<const uchar4*>(&g_bits[(n0 + 2) * NCW + cw4 * 4]);
    uchar4 r3 = *reinterpret_cast<const uchar4*>(&g_bits[(n0 + 3) * NCW + cw4 * 4]);
    float2* dst = &g_xf[((size_t)cw4 * NSYM + s) * 4];
    dst[0] = c_pts[(r0.x << 3) | (r1.x << 2) | (r2.x << 1) | r3.x];
    dst[1] = c_pts[(r0.y << 3) | (r1.y << 2) | (r2.y << 1) | r3.y];
    dst[2] = c_pts[(r0.z << 3) | (r1.z << 2) | (r2.z << 1) | r3.z];
    dst[3] = c_pts[(r0.w << 3) | (r1.w << 2) | (r2.w << 1) | r3.w];
}

// ---------------- LMMSE detect: in-place LU, low register pressure ----------
// Value-identical to the 9-column augmented elimination:
//   * factorization does the same pivot choice and same row ops on A;
//   * RHS columns replay all swaps first, then forward/back solve with stored
//     factors — each scalar FMA has identical operands (LAPACK getrf/getrs
//     relabeling identity), so results match bit-for-bit.
__device__ __forceinline__ void lu_solve(const C2 A[4][4], const C2 dinv[4],
                                         const int piv[4], C2 b[4]) {
    // apply row swaps (static indices, predicated)
#pragma unroll
    for (int k = 0; k < 4; k++) {
        int p = piv[k];
#pragma unroll
        for (int q = 0; q < 4; q++) {
            if (q > k && q == p) { C2 t = b[k]; b[k] = b[q]; b[q] = t; }
        }
    }
    // forward elimination with stored factors (lower triangle of A)
#pragma unroll
    for (int k = 0; k < 4; k++) {
#pragma unroll
        for (int rr = 0; rr < 4; rr++)
            if (rr > k) b[rr] = csub(b[rr], cmul(A[rr][k], b[k]));
    }
    // back substitution (upper triangle + dinv)
#pragma unroll
    for (int rr = 3; rr >= 0; rr--) {
        C2 val = b[rr];
#pragma unroll
        for (int q = 0; q < 4; q++)
            if (q > rr) val = csub(val, cmul(A[rr][q], b[q]));
        b[rr] = cmul(val, dinv[rr]);
    }
}

__global__ void lmmse_kernel(const float* __restrict__ h_re, const float* __restrict__ h_im,
                             const float* __restrict__ n_re, const float* __restrict__ n_im,
                             const float* __restrict__ ebno) {
    int r = blockIdx.x * blockDim.x + threadIdx.x;
    if (r >= NROW) return;

    float no  = 1.0f / (exp10f(ebno[0] * 0.1f) * 4.0f * 0.5f);
    float wsc = sqrtf(no * 0.5f);

    C2 h[4][4];
    const float4* hr4 = reinterpret_cast<const float4*>(h_re + (size_t)r * 16);
    const float4* hi4 = reinterpret_cast<const float4*>(h_im + (size_t)r * 16);
#pragma unroll
    for (int i = 0; i < 4; i++) {
        float4 a = hr4[i], bb = hi4[i];
        h[i][0] = { a.x * RSQRT2, bb.x * RSQRT2 };
        h[i][1] = { a.y * RSQRT2, bb.y * RSQRT2 };
        h[i][2] = { a.z * RSQRT2, bb.z * RSQRT2 };
        h[i][3] = { a.w * RSQRT2, bb.w * RSQRT2 };
    }

    // y = h x + w
    C2 y[4];
    {
        float4 nr = reinterpret_cast<const float4*>(n_re)[r];
        float4 ni = reinterpret_cast<const float4*>(n_im)[r];
        float nrv[4] = { nr.x, nr.y, nr.z, nr.w };
        float niv[4] = { ni.x, ni.y, ni.z, ni.w };
#pragma unroll
        for (int i = 0; i < 4; i++) {
            C2 acc = { nrv[i] * wsc, niv[i] * wsc };
#pragma unroll
            for (int j = 0; j < 4; j++) {
                float2 xj = g_xf[r*4 + j];
                acc = cadd(acc, cmul(h[i][j], {xj.x, xj.y}));
            }
            y[i] = acc;
        }
    }

    // A = h h^H + no I  (same accumulation order as before)
    C2 A[4][4];
#pragma unroll
    for (int i = 0; i < 4; i++) {
#pragma unroll
        for (int k = 0; k < 4; k++) {
            C2 a = { (i == k) ? no : 0.0f, 0.0f };
#pragma unroll
            for (int j = 0; j < 4; j++) a = cadd(a, cmulc(h[i][j], h[k][j]));
            A[i][k] = a;
        }
    }

    // In-place LU with partial pivoting (cabs1 = |re|+|im|); f stored in lower.
    int piv[4];
    C2 dinv[4];
#pragma unroll
    for (int k = 0; k < 4; k++) {
        int p = k;
        float best = fabsf(A[k][k].x) + fabsf(A[k][k].y);
#pragma unroll
        for (int q = 0; q < 4; q++) {
            if (q > k) {
                float m = fabsf(A[q][k].x) + fabsf(A[q][k].y);
                if (m > best) { best = m; p = q; }
            }
        }
        piv[k] = p;
        // full-row swap (static indices, predicated)
#pragma unroll
        for (int q = 0; q < 4; q++) {
            if (q > k && q == p) {
#pragma unroll
                for (int c = 0; c < 4; c++) { C2 t = A[k][c]; A[k][c] = A[q][c]; A[q][c] = t; }
            }
        }
        C2 piv_inv = cinv(A[k][k]);
        dinv[k] = piv_inv;                                 // same value as original dinv
#pragma unroll
        for (int rr = 0; rr < 4; rr++) {
            if (rr > k) {
                C2 f = cmul(A[rr][k], piv_inv);
                A[rr][k] = f;                              // store factor
#pragma unroll
                for (int c = 0; c < 4; c++)
                    if (c > k) A[rr][c] = csub(A[rr][c], cmul(f, A[k][c]));
            }
        }
    }

    // Solve y
    lu_solve(A, dinv, piv, y);

    // Per-UE: solve h column, accumulate x_raw and diag, write compact output
#pragma unroll
    for (int j = 0; j < 4; j++) {
        C2 hc[4];
#pragma unroll
        for (int i = 0; i < 4; i++) hc[i] = h[i][j];
        lu_solve(A, dinv, piv, hc);

        C2 xraw = {0.f, 0.f};
        float d = 0.f;
#pragma unroll
        for (int i = 0; i < 4; i++) {
            xraw = cadd(xraw, cmulc(y[i], h[i][j]));       // conj(h)*z_y
            C2 gw = cmulc(hc[i], h[i][j]);                 // conj(h)*(A^-1 h)
            d += gw.x;
        }
        float inv_d = 1.0f / d;
        float xr = xraw.x * inv_d, xi = xraw.y * inv_d;
        float noe = fmaxf(inv_d - 1.0f, 1e-12f);
        float inv_nv = 1.0f / noe;
        g_dem[r * 4 + j] = make_float4(xr, xi, inv_nv, 0.0f);
    }
}

// ---------------- max-log demap (2 cw per thread; identical expressions) ----
__global__ void demap_kernel() {
    int tid = blockIdx.x * blockDim.x + threadIdx.x;       // s*(NCW/2) + cw2
    if (tid >= NSYM * (NCW / 2)) return;
    int s = tid / (NCW / 2), cw = (tid % (NCW / 2)) * 2;
    int bb = cw >> 2, u = cw & 3;                          // cw even -> same bb for cw,cw+1
    float4 dm0 = g_dem[(bb * NSYM + s) * 4 + u];
    float4 dm1 = g_dem[(bb * NSYM + s) * 4 + u + 1];

    float llr0[4], llr1[4];
    {
        float xr = dm0.x, xi = dm0.y, inv_nv = dm0.z;
        float best0[4] = {3.4e38f, 3.4e38f, 3.4e38f, 3.4e38f};
        float best1[4] = {3.4e38f, 3.4e38f, 3.4e38f, 3.4e38f};
#pragma unroll
        for (int p = 0; p < 16; p++) {
            float dr = xr - c_pts[p].x, di = xi - c_pts[p].y;
            float d2 = dr * dr + di * di;
#pragma unroll
            for (int k = 0; k < 4; k++) {
                if ((p >> (3 - k)) & 1) best1[k] = fminf(best1[k], d2);
                else                    best0[k] = fminf(best0[k], d2);
            }
        }
#pragma unroll
        for (int k = 0; k < 4; k++) llr0[k] = (best1[k] - best0[k]) * inv_nv;
    }
    {
        float xr = dm1.x, xi = dm1.y, inv_nv = dm1.z;
        float best0[4] = {3.4e38f, 3.4e38f, 3.4e38f, 3.4e38f};
        float best1[4] = {3.4e38f, 3.4e38f, 3.4e38f, 3.4e38f};
#pragma unroll
        for (int p = 0; p < 16; p++) {
            float dr = xr - c_pts[p].x, di = xi - c_pts[p].y;
            float d2 = dr * dr + di * di;
#pragma unroll
            for (int k = 0; k < 4; k++) {
                if ((p >> (3 - k)) & 1) best1[k] = fminf(best1[k], d2);
                else                    best0[k] = fminf(best0[k], d2);
            }
        }
#pragma unroll
        for (int k = 0; k < 4; k++) llr1[k] = (best1[k] - best0[k]) * inv_nv;
    }
#pragma unroll
    for (int k = 0; k < 4; k++)
        *reinterpret_cast<float2*>(&g_Lch[(size_t)(s * 4 + k) * NCW + cw]) =
            make_float2(llr0[k], llr1[k]);
}

// ---------------- fused LDPC iteration (float2: 2 cw per thread) ------------
__device__ __forceinline__ float tanh_cl(float m) {
    float a = fminf(fmaxf(0.5f * m, -9.9f), 9.9f);
    float t = tanhf(a);
    return (t >= 0.0f) ? fmaxf(t, 1e-7f) : fminf(t, -1e-7f);
}
__device__ __forceinline__ float2 tanh_cl2(float2 m) {
    return { tanh_cl(m.x), tanh_cl(m.y) };
}

__device__ __forceinline__ float2 ld2(const float* p) {
    return *reinterpret_cast<const float2*>(p);
}

// m_vc for edge e (both lanes); identical per-lane fp order to scalar version
__device__ __forceinline__ float2 edge_msg2(const float* __restrict__ o, int e, int c) {
    if (e < NPE) {
        int v = e / 3, r0 = v * 3;
        float2 a0 = ld2(&o[r0 * NCW + c]);
        float2 a1 = ld2(&o[(r0 + 1) * NCW + c]);
        float2 a2 = ld2(&o[(r0 + 2) * NCW + c]);
        float2 L  = ld2(&g_Lch[v * NCW + c]);
        float2 vt = { ((L.x + a0.x) + a1.x) + a2.x, ((L.y + a0.y) + a1.y) + a2.y };
        int sl = e - r0;
        float2 me = (sl == 0) ? a0 : ((sl == 1) ? a1 : a2);
        return { vt.x - me.x, vt.y - me.y };
    } else {
        int v = KK + (e - NPE);
        float2 cc = ld2(&o[e * NCW + c]);
        float2 L  = ld2(&g_Lch[v * NCW + c]);
        return { (L.x + cc.x) - cc.x, (L.y + cc.y) - cc.y };   // keep (L+c)-c rounding
    }
}

// DIR=0: read g_c2v_a, write g_c2v_b.  DIR=1: read g_c2v_b, write g_c2v_a.
template <int DIR>
__global__ void ldpc_iter_kernel() {
    const float* __restrict__ o = DIR ? g_c2v_b : g_c2v_a;
    float* __restrict__ n       = DIR ? g_c2v_a : g_c2v_b;
    int tid = blockIdx.x * blockDim.x + threadIdx.x;           // j*(NCW/2) + cw2
    if (tid >= MM * (NCW / 2)) return;
    int j = tid / (NCW / 2), c = (tid % (NCW / 2)) * 2;
    int b0 = g_coff[j], b1 = g_coff[j + 1];
    int deg = b1 - b0;

    if (deg <= MAXDEG) {
        float2 t[MAXDEG];
        float2 prod = { 1.0f, 1.0f };
#pragma unroll
        for (int k = 0; k < MAXDEG; k++) {
            if (k < deg) {
                float2 tt = tanh_cl2(edge_msg2(o, g_cedge[b0 + k], c));
                t[k] = tt;
                prod.x *= tt.x; prod.y *= tt.y;
            }
        }
#pragma unroll
        for (int k = 0; k < MAXDEG; k++) {
            if (k < deg) {
                float rx = prod.x / t[k].x, ry = prod.y / t[k].y;
                rx = fminf(fmaxf(rx, -0.999999f), 0.999999f);
                ry = fminf(fmaxf(ry, -0.999999f), 0.999999f);
                *reinterpret_cast<float2*>(&n[g_cedge[b0 + k] * NCW + c]) =
                    make_float2(2.0f * atanhf(rx), 2.0f * atanhf(ry));
            }
        }
    } else {
        // fallback (degree beyond register cache; identical math, recompute)
        float2 prod = { 1.0f, 1.0f };
        for (int k = b0; k < b1; k++) {
            float2 tt = tanh_cl2(edge_msg2(o, g_cedge[k], c));
            prod.x *= tt.x; prod.y *= tt.y;
        }
        for (int k = b0; k < b1; k++) {
            int e = g_cedge[k];
            float2 tt = tanh_cl2(edge_msg2(o, e, c));
            float rx = prod.x / tt.x, ry = prod.y / tt.y;
            rx = fminf(fmaxf(rx, -0.999999f), 0.999999f);
            ry = fminf(fmaxf(ry, -0.999999f), 0.999999f);
            *reinterpret_cast<float2*>(&n[e * NCW + c]) =
                make_float2(2.0f * atanhf(rx), 2.0f * atanhf(ry));
        }
    }
}

// ---------------- final hard decision + transposed write --------------------
// Reads g_c2v_b (final messages after 5 iterations: a->b,b->a,a->b,b->a,a->b)
__global__ void bhat_kernel(float* __restrict__ out) {
    __shared__ float tile[32][33];
    int i0 = blockIdx.x * 32, cw0 = blockIdx.y * 32;
    int tx = threadIdx.x, ty = threadIdx.y;                    // block (32,8)
    for (int yy = ty; yy < 32; yy += 8) {
        int i = i0 + yy, cw = cw0 + tx;
        if (cw < NCW && i < KK) {
            int r0 = i * 3;
            float s = g_Lch[i * NCW + cw];
            s += g_c2v_b[r0 * NCW + cw];
            s += g_c2v_b[(r0 + 1) * NCW + cw];
            s += g_c2v_b[(r0 + 2) * NCW + cw];
            tile[yy][tx] = (s < 0.0f) ? 1.0f : 0.0f;
        }
    }
    __syncthreads();
    for (int yy = ty; yy < 32; yy += 8) {
        int cw = cw0 + yy, i = i0 + tx;
        if (cw < NCW && i < KK)
            out[(size_t)NCW * KK + (size_t)cw * KK + i] = tile[tx][yy];
    }
}

// ---------------- launch ----------------------------------------------------
extern "C" void kernel_launch(void* const* d_in, const int* in_sizes, int n_in,
                              void* d_out, int out_size) {
    int base = n_in - 9;
    const float* ebno = (const float*)d_in[base + 0];
    const int*   b    = (const int*)  d_in[base + 1];
    const int*   cn   = (const int*)  d_in[base + 3];
    const float* h_re = (const float*)d_in[base + 5];
    const float* h_im = (const float*)d_in[base + 6];
    const float* n_re = (const float*)d_in[base + 7];
    const float* n_im = (const float*)d_in[base + 8];
    float* out = (float*)d_out;

    const int T = 256;

    zero_kernel<<<(NEDGE * NCW / 4 + T - 1) / T, T>>>();
    setup_kernel<<<1, 512>>>(cn);

    dim3 tb(32, 8);
    bits_kernel<<<dim3((KK + 31) / 32, NCW / 32), tb>>>(b, out);
    parity_kernel<<<(MM * (NCW / 4) + T - 1) / T, T>>>();
    map_kernel<<<(NSYM * (NCW / 4) + T - 1) / T, T>>>();
    lmmse_kernel<<<(NROW + T - 1) / T, T>>>(h_re, h_im, n_re, n_im, ebno);
    demap_kernel<<<(NSYM * (NCW / 2) + T - 1) / T, T>>>();

    // 5 fused iterations, ping-pong via template direction (a starts zeroed)
    const int G = (MM * (NCW / 2) + T - 1) / T;
    ldpc_iter_kernel<0><<<G, T>>>();   // a -> b
    ldpc_iter_kernel<1><<<G, T>>>();   // b -> a
    ldpc_iter_kernel<0><<<G, T>>>();   // a -> b
    ldpc_iter_kernel<1><<<G, T>>>();   // b -> a
    ldpc_iter_kernel<0><<<G, T>>>();   // a -> b  (final in g_c2v_b)

    bhat_kernel<<<dim3((KK + 31) / 32, NCW / 32), tb>>>(out);
}

// round 14
// speedup vs baseline: 2.1634x; 1.1133x over previous
#include <cuda_runtime.h>
#include <math.h>

// Problem constants (fixed by the reference)
#define NN      1000      // codeword length
#define KK      500       // info bits
#define MM      500       // parity checks
#define NSYM    250       // NN / BPS
#define NITER   5
#define NCW     4000      // BATCH * NUE  (codewords)
#define NROW    250000    // BATCH * NSYM (LMMSE rows)
#define NPE     1500      // P edges (3 per info var, row-major order)
#define NEDGE   2000
#define MAXDEG  12        // max check degree handled in registers
#define MAXSLOT 16        // capacity per check in setup
#define RSQRT2  0.70710678118654752f

// ---------------- scratch (device globals; no allocation allowed) -----------
__device__ unsigned char g_bits[NN * NCW];           // 4 MB  bits [n][cw]
__device__ float2        g_xf[NROW * 4];             // 8 MB  tx symbols
__device__ float4        g_dem[NROW * 4];            // 16 MB {xr, xi, inv_nv, -}
__device__ float         g_Lch[NN * NCW];            // 16 MB channel LLRs [n][cw]
__device__ float         g_c2v_a[NEDGE * NCW];       // 32 MB c2v ping
__device__ float         g_c2v_b[NEDGE * NCW];       // 32 MB c2v pong
__device__ int           g_coff[MM + 1];             // check CSR offsets
__device__ int           g_cedge[NEDGE];             // edge ids per check (ascending)

// 16-QAM constellation (matches reference POINTS)
__constant__ float2 c_pts[16] = {
    { 0.31622776601683794f,  0.31622776601683794f}, { 0.31622776601683794f,  0.9486832980505138f},
    { 0.9486832980505138f,   0.31622776601683794f}, { 0.9486832980505138f,   0.9486832980505138f},
    { 0.31622776601683794f, -0.31622776601683794f}, { 0.31622776601683794f, -0.9486832980505138f},
    { 0.9486832980505138f,  -0.31622776601683794f}, { 0.9486832980505138f,  -0.9486832980505138f},
    {-0.31622776601683794f,  0.31622776601683794f}, {-0.31622776601683794f,  0.9486832980505138f},
    {-0.9486832980505138f,   0.31622776601683794f}, {-0.9486832980505138f,   0.9486832980505138f},
    {-0.31622776601683794f, -0.31622776601683794f}, {-0.31622776601683794f, -0.9486832980505138f},
    {-0.9486832980505138f,  -0.31622776601683794f}, {-0.9486832980505138f,  -0.9486832980505138f}
};

// ---------------- complex helpers -------------------------------------------
struct C2 { float x, y; };
__device__ __forceinline__ C2 cmul(C2 a, C2 b)  { return { a.x*b.x - a.y*b.y, a.x*b.y + a.y*b.x }; }
__device__ __forceinline__ C2 cmulc(C2 a, C2 b) { return { a.x*b.x + a.y*b.y, a.y*b.x - a.x*b.y }; } // a*conj(b)
__device__ __forceinline__ C2 cadd(C2 a, C2 b)  { return { a.x + b.x, a.y + b.y }; }
__device__ __forceinline__ C2 csub(C2 a, C2 b)  { return { a.x - b.x, a.y - b.y }; }
__device__ __forceinline__ C2 cinv(C2 a) { float s = 1.0f/(a.x*a.x + a.y*a.y); return { a.x*s, -a.y*s }; }

// ---------------- setup: check-side CSR (atomic slots + per-check sort) -----
// Final g_cedge order per check: ascending edge id (== stable scan order),
// identity edge NPE+j naturally last (largest id). Deterministic.
__global__ void setup_kernel(const int* __restrict__ cn) {
    __shared__ int cnt[MM];
    __shared__ int coff[MM + 1];
    __shared__ int cur[MM];
    __shared__ int slots[MM * MAXSLOT / 4];  // not enough smem for full; use global order below
    (void)slots;
    int t = threadIdx.x;
    for (int i = t; i < MM; i += blockDim.x) cnt[i] = 0;
    __syncthreads();
    for (int e = t; e < NPE; e += blockDim.x) atomicAdd(&cnt[cn[e]], 1);
    __syncthreads();
    if (t == 0) {
        int a = 0;
        for (int j = 0; j < MM; j++) { coff[j] = a; a += cnt[j] + 1; }  // +1 identity edge
        coff[MM] = a;
    }
    __syncthreads();
    for (int i = t; i < MM; i += blockDim.x) cur[i] = coff[i];
    __syncthreads();
    // place P-edges (nondeterministic slot order within a check)
    for (int e = t; e < NPE; e += blockDim.x) {
        int j = cn[e];
        int pos = atomicAdd(&cur[j], 1);
        g_cedge[pos] = e;
    }
    // place identity edge at the reserved last slot
    for (int j = t; j < MM; j += blockDim.x)
        g_cedge[coff[j + 1] - 1] = NPE + j;
    __syncthreads();
    // per-check insertion sort of the P-edge span (<= MAXSLOT-1 elems) -> deterministic
    for (int j = t; j < MM; j += blockDim.x) {
        int b0 = coff[j], b1 = coff[j + 1] - 1;     // exclude identity slot
        for (int a = b0 + 1; a < b1; a++) {
            int key = g_cedge[a];
            int q = a - 1;
            while (q >= b0 && g_cedge[q] > key) { g_cedge[q + 1] = g_cedge[q]; q--; }
            g_cedge[q + 1] = key;
        }
    }
    for (int i = t; i <= MM; i += blockDim.x) g_coff[i] = coff[i];
}

// ---------------- bits: copy bf to out + transpose to [n][cw] ---------------
__global__ void bits_kernel(const int* __restrict__ b, float* __restrict__ out) {
    __shared__ unsigned char tile[32][33];
    int i0 = blockIdx.x * 32, cw0 = blockIdx.y * 32;
    int tx = threadIdx.x, ty = threadIdx.y;                // block (32,8)
    for (int yy = ty; yy < 32; yy += 8) {
        int cw = cw0 + yy, i = i0 + tx;
        if (cw < NCW && i < KK) {
            int v = b[cw * KK + i];
            out[cw * KK + i] = (float)v;                   // bf half of output (exact)
            tile[yy][tx] = (unsigned char)v;
        }
    }
    __syncthreads();
    for (int yy = ty; yy < 32; yy += 8) {
        int i = i0 + yy, cw = cw0 + tx;
        if (cw < NCW && i < KK) g_bits[i * NCW + cw] = tile[tx][yy];
    }
}

// ---------------- parity: XOR over check's P-edges (4 cw per thread) --------
__global__ void parity_kernel() {
    int tid = blockIdx.x * blockDim.x + threadIdx.x;       // j*(NCW/4) + cw4
    if (tid >= MM * (NCW / 4)) return;
    int j = tid / (NCW / 4), cw4 = tid % (NCW / 4);
    int b0 = g_coff[j], b1 = g_coff[j + 1] - 1;            // exclude identity edge
    unsigned int acc = 0;
    for (int k = b0; k < b1; k++) {
        int e = g_cedge[k];
        acc ^= *reinterpret_cast<const unsigned int*>(&g_bits[(e / 3) * NCW + cw4 * 4]);
    }
    *reinterpret_cast<unsigned int*>(&g_bits[(KK + j) * NCW + cw4 * 4]) = acc & 0x01010101u;
}

// ---------------- map: 4 bits -> 16QAM symbol (4 cw per thread) --------------
__global__ void map_kernel() {
    int tid = blockIdx.x * blockDim.x + threadIdx.x;       // s*(NCW/4) + cw4
    if (tid >= NSYM * (NCW / 4)) return;
    int s = tid / (NCW / 4), cw4 = tid % (NCW / 4);        // bb = cw>>2 = cw4, u = cw&3
    int n0 = s * 4;
    uchar4 r0 = *reinterpret_cast<const uchar4*>(&g_bits[ n0      * NCW + cw4 * 4]);
    uchar4 r1 = *reinterpret_cast<const uchar4*>(&g_bits[(n0 + 1) * NCW + cw4 * 4]);
    uchar4 r2 = *reinterpret_cast<const uchar4*>(&g_bits[(n0 + 2) * NCW + cw4 * 4]);
    uchar4 r3 = *reinterpret_cast<const uchar4*>(&g_bits[(n0 + 3) * NCW + cw4 * 4]);
    float2* dst = &g_xf[((size_t)cw4 * NSYM + s) * 4];
    dst[0] = c_pts[(r0.x << 3) | (r1.x << 2) | (r2.x << 1) | r3.x];
    dst[1] = c_pts[(r0.y << 3) | (r1.y << 2) | (r2.y << 1) | r3.y];
    dst[2] = c_pts[(r0.z << 3) | (r1.z << 2) | (r2.z << 1) | r3.z];
    dst[3] = c_pts[(r0.w << 3) | (r1.w << 2) | (r2.w << 1) | r3.w];
}

// ---------------- LMMSE detect: in-place LU, low register pressure ----------
__device__ __forceinline__ void lu_solve(const C2 A[4][4], const C2 dinv[4],
                                         const int piv[4], C2 b[4]) {
#pragma unroll
    for (int k = 0; k < 4; k++) {
        int p = piv[k];
#pragma unroll
        for (int q = 0; q < 4; q++) {
            if (q > k && q == p) { C2 t = b[k]; b[k] = b[q]; b[q] = t; }
        }
    }
#pragma unroll
    for (int k = 0; k < 4; k++) {
#pragma unroll
        for (int rr = 0; rr < 4; rr++)
            if (rr > k) b[rr] = csub(b[rr], cmul(A[rr][k], b[k]));
    }
#pragma unroll
    for (int rr = 3; rr >= 0; rr--) {
        C2 val = b[rr];
#pragma unroll
        for (int q = 0; q < 4; q++)
            if (q > rr) val = csub(val, cmul(A[rr][q], b[q]));
        b[rr] = cmul(val, dinv[rr]);
    }
}

__global__ void lmmse_kernel(const float* __restrict__ h_re, const float* __restrict__ h_im,
                             const float* __restrict__ n_re, const float* __restrict__ n_im,
                             const float* __restrict__ ebno) {
    int r = blockIdx.x * blockDim.x + threadIdx.x;
    if (r >= NROW) return;

    float no  = 1.0f / (exp10f(ebno[0] * 0.1f) * 4.0f * 0.5f);
    float wsc = sqrtf(no * 0.5f);

    C2 h[4][4];
    const float4* hr4 = reinterpret_cast<const float4*>(h_re + (size_t)r * 16);
    const float4* hi4 = reinterpret_cast<const float4*>(h_im + (size_t)r * 16);
#pragma unroll
    for (int i = 0; i < 4; i++) {
        float4 a = hr4[i], bb = hi4[i];
        h[i][0] = { a.x * RSQRT2, bb.x * RSQRT2 };
        h[i][1] = { a.y * RSQRT2, bb.y * RSQRT2 };
        h[i][2] = { a.z * RSQRT2, bb.z * RSQRT2 };
        h[i][3] = { a.w * RSQRT2, bb.w * RSQRT2 };
    }

    // y = h x + w
    C2 y[4];
    {
        float4 nr = reinterpret_cast<const float4*>(n_re)[r];
        float4 ni = reinterpret_cast<const float4*>(n_im)[r];
        float nrv[4] = { nr.x, nr.y, nr.z, nr.w };
        float niv[4] = { ni.x, ni.y, ni.z, ni.w };
#pragma unroll
        for (int i = 0; i < 4; i++) {
            C2 acc = { nrv[i] * wsc, niv[i] * wsc };
#pragma unroll
            for (int j = 0; j < 4; j++) {
                float2 xj = g_xf[r*4 + j];
                acc = cadd(acc, cmul(h[i][j], {xj.x, xj.y}));
            }
            y[i] = acc;
        }
    }

    // A = h h^H + no I  (same accumulation order as before)
    C2 A[4][4];
#pragma unroll
    for (int i = 0; i < 4; i++) {
#pragma unroll
        for (int k = 0; k < 4; k++) {
            C2 a = { (i == k) ? no : 0.0f, 0.0f };
#pragma unroll
            for (int j = 0; j < 4; j++) a = cadd(a, cmulc(h[i][j], h[k][j]));
            A[i][k] = a;
        }
    }

    // In-place LU with partial pivoting (cabs1 = |re|+|im|); f stored in lower.
    int piv[4];
    C2 dinv[4];
#pragma unroll
    for (int k = 0; k < 4; k++) {
        int p = k;
        float best = fabsf(A[k][k].x) + fabsf(A[k][k].y);
#pragma unroll
        for (int q = 0; q < 4; q++) {
            if (q > k) {
                float m = fabsf(A[q][k].x) + fabsf(A[q][k].y);
                if (m > best) { best = m; p = q; }
            }
        }
        piv[k] = p;
#pragma unroll
        for (int q = 0; q < 4; q++) {
            if (q > k && q == p) {
#pragma unroll
                for (int c = 0; c < 4; c++) { C2 t = A[k][c]; A[k][c] = A[q][c]; A[q][c] = t; }
            }
        }
        C2 piv_inv = cinv(A[k][k]);
        dinv[k] = piv_inv;
#pragma unroll
        for (int rr = 0; rr < 4; rr++) {
            if (rr > k) {
                C2 f = cmul(A[rr][k], piv_inv);
                A[rr][k] = f;
#pragma unroll
                for (int c = 0; c < 4; c++)
                    if (c > k) A[rr][c] = csub(A[rr][c], cmul(f, A[k][c]));
            }
        }
    }

    lu_solve(A, dinv, piv, y);

#pragma unroll
    for (int j = 0; j < 4; j++) {
        C2 hc[4];
#pragma unroll
        for (int i = 0; i < 4; i++) hc[i] = h[i][j];
        lu_solve(A, dinv, piv, hc);

        C2 xraw = {0.f, 0.f};
        float d = 0.f;
#pragma unroll
        for (int i = 0; i < 4; i++) {
            xraw = cadd(xraw, cmulc(y[i], h[i][j]));
            C2 gw = cmulc(hc[i], h[i][j]);
            d += gw.x;
        }
        float inv_d = 1.0f / d;
        float xr = xraw.x * inv_d, xi = xraw.y * inv_d;
        float noe = fmaxf(inv_d - 1.0f, 1e-12f);
        float inv_nv = 1.0f / noe;
        g_dem[r * 4 + j] = make_float4(xr, xi, inv_nv, 0.0f);
    }
}

// ---------------- max-log demap (2 cw per thread; identical expressions) ----
__global__ void demap_kernel() {
    int tid = blockIdx.x * blockDim.x + threadIdx.x;       // s*(NCW/2) + cw2
    if (tid >= NSYM * (NCW / 2)) return;
    int s = tid / (NCW / 2), cw = (tid % (NCW / 2)) * 2;
    int bb = cw >> 2, u = cw & 3;
    float4 dm0 = g_dem[(bb * NSYM + s) * 4 + u];
    float4 dm1 = g_dem[(bb * NSYM + s) * 4 + u + 1];

    float llr0[4], llr1[4];
    {
        float xr = dm0.x, xi = dm0.y, inv_nv = dm0.z;
        float best0[4] = {3.4e38f, 3.4e38f, 3.4e38f, 3.4e38f};
        float best1[4] = {3.4e38f, 3.4e38f, 3.4e38f, 3.4e38f};
#pragma unroll
        for (int p = 0; p < 16; p++) {
            float dr = xr - c_pts[p].x, di = xi - c_pts[p].y;
            float d2 = dr * dr + di * di;
#pragma unroll
            for (int k = 0; k < 4; k++) {
                if ((p >> (3 - k)) & 1) best1[k] = fminf(best1[k], d2);
                else                    best0[k] = fminf(best0[k], d2);
            }
        }
#pragma unroll
        for (int k = 0; k < 4; k++) llr0[k] = (best1[k] - best0[k]) * inv_nv;
    }
    {
        float xr = dm1.x, xi = dm1.y, inv_nv = dm1.z;
        float best0[4] = {3.4e38f, 3.4e38f, 3.4e38f, 3.4e38f};
        float best1[4] = {3.4e38f, 3.4e38f, 3.4e38f, 3.4e38f};
#pragma unroll
        for (int p = 0; p < 16; p++) {
            float dr = xr - c_pts[p].x, di = xi - c_pts[p].y;
            float d2 = dr * dr + di * di;
#pragma unroll
            for (int k = 0; k < 4; k++) {
                if ((p >> (3 - k)) & 1) best1[k] = fminf(best1[k], d2);
                else                    best0[k] = fminf(best0[k], d2);
            }
        }
#pragma unroll
        for (int k = 0; k < 4; k++) llr1[k] = (best1[k] - best0[k]) * inv_nv;
    }
#pragma unroll
    for (int k = 0; k < 4; k++)
        *reinterpret_cast<float2*>(&g_Lch[(size_t)(s * 4 + k) * NCW + cw]) =
            make_float2(llr0[k], llr1[k]);
}

// ---------------- fused LDPC iteration (float4: 4 cw per thread) ------------
__device__ __forceinline__ float tanh_cl(float m) {
    float a = fminf(fmaxf(0.5f * m, -9.9f), 9.9f);
    float t = tanhf(a);
    return (t >= 0.0f) ? fmaxf(t, 1e-7f) : fminf(t, -1e-7f);
}
__device__ __forceinline__ float4 tanh_cl4(float4 m) {
    return { tanh_cl(m.x), tanh_cl(m.y), tanh_cl(m.z), tanh_cl(m.w) };
}
__device__ __forceinline__ float4 ld4(const float* p) {
    return *reinterpret_cast<const float4*>(p);
}

// m_vc for edge e (4 lanes); identical per-lane fp order to scalar version
__device__ __forceinline__ float4 edge_msg4(const float* __restrict__ o, int e, int c) {
    if (e < NPE) {
        int v = e / 3, r0 = v * 3;
        float4 a0 = ld4(&o[r0 * NCW + c]);
        float4 a1 = ld4(&o[(r0 + 1) * NCW + c]);
        float4 a2 = ld4(&o[(r0 + 2) * NCW + c]);
        float4 L  = ld4(&g_Lch[v * NCW + c]);
        float4 vt = { ((L.x + a0.x) + a1.x) + a2.x, ((L.y + a0.y) + a1.y) + a2.y,
                      ((L.z + a0.z) + a1.z) + a2.z, ((L.w + a0.w) + a1.w) + a2.w };
        int sl = e - r0;
        float4 me = (sl == 0) ? a0 : ((sl == 1) ? a1 : a2);
        return { vt.x - me.x, vt.y - me.y, vt.z - me.z, vt.w - me.w };
    } else {
        int v = KK + (e - NPE);
        float4 cc = ld4(&o[e * NCW + c]);
        float4 L  = ld4(&g_Lch[v * NCW + c]);
        return { (L.x + cc.x) - cc.x, (L.y + cc.y) - cc.y,
                 (L.z + cc.z) - cc.z, (L.w + cc.w) - cc.w };   // keep (L+c)-c rounding
    }
}

__device__ __forceinline__ void write_msgs4(float* __restrict__ n, int e, int c,
                                            float4 prod, float4 t) {
    float rx = prod.x / t.x, ry = prod.y / t.y, rz = prod.z / t.z, rw = prod.w / t.w;
    rx = fminf(fmaxf(rx, -0.999999f), 0.999999f);
    ry = fminf(fmaxf(ry, -0.999999f), 0.999999f);
    rz = fminf(fmaxf(rz, -0.999999f), 0.999999f);
    rw = fminf(fmaxf(rw, -0.999999f), 0.999999f);
    *reinterpret_cast<float4*>(&n[e * NCW + c]) =
        make_float4(2.0f * atanhf(rx), 2.0f * atanhf(ry),
                    2.0f * atanhf(rz), 2.0f * atanhf(rw));
}

// Iteration 0: c2v == 0 everywhere, so m_vc == Lch[v] bit-exactly
// (L+0+0+0-0 == L for all finite L; Lch is never -0).  No c2v reads needed.
__global__ void ldpc_iter0_kernel() {
    float* __restrict__ n = g_c2v_b;
    int tid = blockIdx.x * blockDim.x + threadIdx.x;           // j*(NCW/4) + cw4
    if (tid >= MM * (NCW / 4)) return;
    int j = tid / (NCW / 4), c = (tid % (NCW / 4)) * 4;
    int b0 = g_coff[j], b1 = g_coff[j + 1];
    int deg = b1 - b0;

    float4 t[MAXDEG];
    float4 prod = { 1.0f, 1.0f, 1.0f, 1.0f };
#pragma unroll
    for (int k = 0; k < MAXDEG; k++) {
        if (k < deg) {
            int e = g_cedge[b0 + k];
            int v = (e < NPE) ? (e / 3) : (KK + (e - NPE));
            float4 tt = tanh_cl4(ld4(&g_Lch[v * NCW + c]));
            t[k] = tt;
            prod.x *= tt.x; prod.y *= tt.y; prod.z *= tt.z; prod.w *= tt.w;
        }
    }
    for (int k = MAXDEG; k < deg; k++) {                       // rare fallback tail
        int e = g_cedge[b0 + k];
        int v = (e < NPE) ? (e / 3) : (KK + (e - NPE));
        float4 tt = tanh_cl4(ld4(&g_Lch[v * NCW + c]));
        prod.x *= tt.x; prod.y *= tt.y; prod.z *= tt.z; prod.w *= tt.w;
    }
#pragma unroll
    for (int k = 0; k < MAXDEG; k++) {
        if (k < deg) write_msgs4(n, g_cedge[b0 + k], c, prod, t[k]);
    }
    for (int k = MAXDEG; k < deg; k++) {
        int e = g_cedge[b0 + k];
        int v = (e < NPE) ? (e / 3) : (KK + (e - NPE));
        float4 tt = tanh_cl4(ld4(&g_Lch[v * NCW + c]));
        write_msgs4(n, e, c, prod, tt);
    }
}

// DIR=0: read g_c2v_a, write g_c2v_b.  DIR=1: read g_c2v_b, write g_c2v_a.
template <int DIR>
__global__ void ldpc_iter_kernel() {
    const float* __restrict__ o = DIR ? g_c2v_b : g_c2v_a;
    float* __restrict__ n       = DIR ? g_c2v_a : g_c2v_b;
    int tid = blockIdx.x * blockDim.x + threadIdx.x;           // j*(NCW/4) + cw4
    if (tid >= MM * (NCW / 4)) return;
    int j = tid / (NCW / 4), c = (tid % (NCW / 4)) * 4;
    int b0 = g_coff[j], b1 = g_coff[j + 1];
    int deg = b1 - b0;

    if (deg <= MAXDEG) {
        float4 t[MAXDEG];
        float4 prod = { 1.0f, 1.0f, 1.0f, 1.0f };
#pragma unroll
        for (int k = 0; k < MAXDEG; k++) {
            if (k < deg) {
                float4 tt = tanh_cl4(edge_msg4(o, g_cedge[b0 + k], c));
                t[k] = tt;
                prod.x *= tt.x; prod.y *= tt.y; prod.z *= tt.z; prod.w *= tt.w;
            }
        }
#pragma unroll
        for (int k = 0; k < MAXDEG; k++) {
            if (k < deg) write_msgs4(n, g_cedge[b0 + k], c, prod, t[k]);
        }
    } else {
        // fallback (degree beyond register cache; identical math, recompute)
        float4 prod = { 1.0f, 1.0f, 1.0f, 1.0f };
        for (int k = b0; k < b1; k++) {
            float4 tt = tanh_cl4(edge_msg4(o, g_cedge[k], c));
            prod.x *= tt.x; prod.y *= tt.y; prod.z *= tt.z; prod.w *= tt.w;
        }
        for (int k = b0; k < b1; k++) {
            int e = g_cedge[k];
            float4 tt = tanh_cl4(edge_msg4(o, e, c));
            write_msgs4(n, e, c, prod, tt);
        }
    }
}

// ---------------- final hard decision + transposed write --------------------
// Reads g_c2v_b (final messages after it0->b, b->a, a->b, b->a, a->b)
__global__ void bhat_kernel(float* __restrict__ out) {
    __shared__ float tile[32][33];
    int i0 = blockIdx.x * 32, cw0 = blockIdx.y * 32;
    int tx = threadIdx.x, ty = threadIdx.y;                    // block (32,8)
    for (int yy = ty; yy < 32; yy += 8) {
        int i = i0 + yy, cw = cw0 + tx;
        if (cw < NCW && i < KK) {
            int r0 = i * 3;
            float s = g_Lch[i * NCW + cw];
            s += g_c2v_b[r0 * NCW + cw];
            s += g_c2v_b[(r0 + 1) * NCW + cw];
            s += g_c2v_b[(r0 + 2) * NCW + cw];
            tile[yy][tx] = (s < 0.0f) ? 1.0f : 0.0f;
        }
    }
    __syncthreads();
    for (int yy = ty; yy < 32; yy += 8) {
        int cw = cw0 + yy, i = i0 + tx;
        if (cw < NCW && i < KK)
            out[(size_t)NCW * KK + (size_t)cw * KK + i] = tile[tx][yy];
    }
}

// ---------------- launch ----------------------------------------------------
extern "C" void kernel_launch(void* const* d_in, const int* in_sizes, int n_in,
                              void* d_out, int out_size) {
    int base = n_in - 9;
    const float* ebno = (const float*)d_in[base + 0];
    const int*   b    = (const int*)  d_in[base + 1];
    const int*   cn   = (const int*)  d_in[base + 3];
    const float* h_re = (const float*)d_in[base + 5];
    const float* h_im = (const float*)d_in[base + 6];
    const float* n_re = (const float*)d_in[base + 7];
    const float* n_im = (const float*)d_in[base + 8];
    float* out = (float*)d_out;

    const int T = 256;

    setup_kernel<<<1, 512>>>(cn);

    dim3 tb(32, 8);
    bits_kernel<<<dim3((KK + 31) / 32, NCW / 32), tb>>>(b, out);
    parity_kernel<<<(MM * (NCW / 4) + T - 1) / T, T>>>();
    map_kernel<<<(NSYM * (NCW / 4) + T - 1) / T, T>>>();
    lmmse_kernel<<<(NROW + T - 1) / T, T>>>(h_re, h_im, n_re, n_im, ebno);
    demap_kernel<<<(NSYM * (NCW / 2) + T - 1) / T, T>>>();

    // 5 iterations: specialized it0 (implicit-zero c2v) then 4 ping-pongs
    const int G4 = (MM * (NCW / 4) + T - 1) / T;
    ldpc_iter0_kernel<<<G4, T>>>();    //      -> b
    ldpc_iter_kernel<1><<<G4, T>>>();  // b -> a
    ldpc_iter_kernel<0><<<G4, T>>>();  // a -> b
    ldpc_iter_kernel<1><<<G4, T>>>();  // b -> a
    ldpc_iter_kernel<0><<<G4, T>>>();  // a -> b  (final in g_c2v_b)

    bhat_kernel<<<dim3((KK + 31) / 32, NCW / 32), tb>>>(out);
}